// round 12
// baseline (speedup 1.0000x reference)
#include <cuda_runtime.h>
#include <cuda_bf16.h>
#include <math.h>

// ---------------- problem constants ----------------
#define BB 2
#define NN_NODES 512
#define FDIM 1024
#define HEADS 4
#define DH 256
#define AH 256
#define HID 512
#define OUTF 128
#define NCLS 10
#define NN2 (NN_NODES*NN_NODES)          // 262144
#define KSEL 209715                       // int(0.8 * N*N)
#define THR_IDX (NN2 - KSEL)              // 52429
#define BN_M (BB*NN_NODES)
#define PJOFF (BB*NN_NODES*AH)

// ---------------- fp32 scratch ----------------
__device__ float g_hp [BB*NN_NODES*FDIM];
__device__ float g_si [BB*HEADS*NN_NODES];
__device__ float g_sj [BB*HEADS*NN_NODES];
__device__ float g_pij[2*BB*NN_NODES*AH];
__device__ float g_sc [BB*NN2];
__device__ float g_h1b[BB*NN_NODES*HID];
__device__ float g_h2b[BB*NN_NODES*OUTF];
__device__ float g_part[BB*64];
__device__ float g_inv[BB];
__device__ unsigned g_mxu[BB];
__device__ unsigned g_sjmx[BB*HEADS];
__device__ unsigned g_h16[BB][65536];
__device__ unsigned g_hi16[BB];
__device__ int g_selrank[BB];
__device__ unsigned g_thrE[BB];

// ---------------- bf16 hi/lo plane arena ----------------
#define SZ_X    (BB*NN_NODES*FDIM)
#define SZ_WG   (FDIM*FDIM)
#define SZ_W1   (AH*2*FDIM)
#define SZ_GC1  (HID*FDIM)
#define SZ_GC2  (OUTF*HID)
#define SZ_HP   (BB*NN_NODES*FDIM)
#define SZ_AL   (BB*HEADS*NN2)
#define SZ_NF   (BB*NN_NODES*FDIM)
#define SZ_ADJ  (BB*NN2)
#define SZ_H1   (BB*NN_NODES*FDIM)
#define SZ_H1B  (BB*NN_NODES*HID)
#define SZ_H2   (BB*NN_NODES*HID)

#define O_XH   ((size_t)0)
#define O_XL   (O_XH   + SZ_X)
#define O_WGH  (O_XL   + SZ_X)
#define O_WGL  (O_WGH  + SZ_WG)
#define O_W1H  (O_WGL  + SZ_WG)
#define O_W1L  (O_W1H  + SZ_W1)
#define O_GC1H (O_W1L  + SZ_W1)
#define O_GC1L (O_GC1H + SZ_GC1)
#define O_GC2H (O_GC1L + SZ_GC1)
#define O_GC2L (O_GC2H + SZ_GC2)
#define O_HPH  (O_GC2L + SZ_GC2)
#define O_HPL  (O_HPH  + SZ_HP)
#define O_ALH  (O_HPL  + SZ_HP)
#define O_ALL  (O_ALH  + SZ_AL)
#define O_NFH  (O_ALL  + SZ_AL)
#define O_NFL  (O_NFH  + SZ_NF)
#define O_ADJH (O_NFL  + SZ_NF)
#define O_ADJL (O_ADJH + SZ_ADJ)
#define O_H1H  (O_ADJL + SZ_ADJ)
#define O_H1L  (O_H1H  + SZ_H1)
#define O_H1BH (O_H1L  + SZ_H1)
#define O_H1BL (O_H1BH + SZ_H1B)
#define O_H2H  (O_H1BL + SZ_H1B)
#define O_H2L  (O_H2H  + SZ_H2)
#define O_END  (O_H2L  + SZ_H2)

__device__ __nv_bfloat16 g_bf[O_END];

// ---------------- helpers ----------------
__device__ __forceinline__ unsigned enc_f(float f) {
    unsigned u = __float_as_uint(f);
    return (u & 0x80000000u) ? ~u : (u | 0x80000000u);
}
__device__ __forceinline__ float dec_f(unsigned e) {
    unsigned u = (e & 0x80000000u) ? (e ^ 0x80000000u) : ~e;
    return __uint_as_float(u);
}
__device__ __forceinline__ void splitw(float v, __nv_bfloat16& h, __nv_bfloat16& l) {
    h = __float2bfloat16_rn(v);
    l = __float2bfloat16_rn(v - __bfloat162float(h));
}

__device__ __forceinline__ void ldsm4(unsigned addr, unsigned& r0, unsigned& r1,
                                      unsigned& r2, unsigned& r3)
{
    asm volatile("ldmatrix.sync.aligned.m8n8.x4.shared.b16 {%0,%1,%2,%3}, [%4];"
                 : "=r"(r0), "=r"(r1), "=r"(r2), "=r"(r3) : "r"(addr));
}
__device__ __forceinline__ void ldsm4t(unsigned addr, unsigned& r0, unsigned& r1,
                                       unsigned& r2, unsigned& r3)
{
    asm volatile("ldmatrix.sync.aligned.m8n8.x4.trans.shared.b16 {%0,%1,%2,%3}, [%4];"
                 : "=r"(r0), "=r"(r1), "=r"(r2), "=r"(r3) : "r"(addr));
}

// ---------------- f32 -> bf16 hi/lo plane converter ----------------
__global__ void conv_kernel(const float* __restrict__ src,
                            __nv_bfloat16* __restrict__ H,
                            __nv_bfloat16* __restrict__ L, int n4)
{
    int i = blockIdx.x * blockDim.x + threadIdx.x;
    if (i >= n4) return;
    float4 v = ((const float4*)src)[i];
    __nv_bfloat162 h0 = __floats2bfloat162_rn(v.x, v.y);
    __nv_bfloat162 h1 = __floats2bfloat162_rn(v.z, v.w);
    float2 f0 = __bfloat1622float2(h0);
    float2 f1 = __bfloat1622float2(h1);
    __nv_bfloat162 l0 = __floats2bfloat162_rn(v.x - f0.x, v.y - f0.y);
    __nv_bfloat162 l1 = __floats2bfloat162_rn(v.z - f1.x, v.w - f1.y);
    *reinterpret_cast<__nv_bfloat162*>(H + 4*i)     = h0;
    *reinterpret_cast<__nv_bfloat162*>(H + 4*i + 2) = h1;
    *reinterpret_cast<__nv_bfloat162*>(L + 4*i)     = l0;
    *reinterpret_cast<__nv_bfloat162*>(L + 4*i + 2) = l1;
}

// ---------------- bf16 split-operand tensor-core GEMM ----------------
// BM=128, BN=64, 256 threads, warp tile 32x32, K-tile 32, double-buffered.
// C[m,n] = sum_k A[m,k] * (TRANSB ? B[n,k] : B[k,n])  (+bias) (*scale[z1])
#define AP  40   // [row][k] pitch in bf16 (A; B when TRANSB) -> 80B rows
#define BPN 72   // [k][n] pitch in bf16 (B when !TRANSB) -> 144B rows
#define ASZ 5120   // elems per A plane-buffer (128*40)
#define BSZ 2560   // elems per B plane-buffer (max(64*40, 32*72))
#define GEMM_SMEM ((2*ASZ*2 + 2*BSZ*2) * 2 * 2)  // bytes = 61440
template<bool TRANSB, bool BIAS, bool SCALE, bool WF32, bool WHL>
__global__ void __launch_bounds__(256) mma_gemm(
    const __nv_bfloat16* __restrict__ AH_, const __nv_bfloat16* __restrict__ AL_, int lda,
    const __nv_bfloat16* __restrict__ BH_, const __nv_bfloat16* __restrict__ BL_, int ldb,
    long sA, long sA2, long sB, long sB2,
    const float* __restrict__ bias, const float* __restrict__ scale,
    float* __restrict__ C, __nv_bfloat16* __restrict__ CH, __nv_bfloat16* __restrict__ CL,
    int ldc, long sC, long sC2, int K, int zdiv)
{
    extern __shared__ __align__(16) char smraw[];
    __nv_bfloat16* Ahs = (__nv_bfloat16*)smraw;      // [2][ASZ]
    __nv_bfloat16* Als = Ahs + 2 * ASZ;              // [2][ASZ]
    __nv_bfloat16* Bhs = Als + 2 * ASZ;              // [2][BSZ]
    __nv_bfloat16* Bls = Bhs + 2 * BSZ;              // [2][BSZ]

    const int bz = blockIdx.z;
    const int z1 = bz / zdiv, z2 = bz % zdiv;
    const long offA_g = z1 * sA + z2 * sA2;
    const long offB_g = z1 * sB + z2 * sB2;
    const long offC_g = z1 * sC + z2 * sC2;
    const __nv_bfloat16* Ah_g = AH_ + offA_g;
    const __nv_bfloat16* Al_g = AL_ + offA_g;
    const __nv_bfloat16* Bh_g = BH_ + offB_g;
    const __nv_bfloat16* Bl_g = BL_ + offB_g;

    const int m0 = blockIdx.y * 128;
    const int n0 = blockIdx.x * 64;
    const int tid = threadIdx.x;
    const int lane = tid & 31;
    const int wid  = tid >> 5;
    const int wm = wid >> 1, wn = wid & 1;   // warp tile: rows wm*32..+32, cols wn*32..+32
    const int g  = lane >> 2;
    const int tg = lane & 3;

    // staging indices
    const int a_r = tid >> 2;             // 0..63 (A rows a_r and a_r+64)
    const int a_c8 = (tid & 3) * 8;       // k-chunk
    const int b_kr = tid >> 3;            // 0..31 (!TRANSB)
    const int b_nc = (tid & 7) * 8;       // n-chunk

    // ldmatrix per-lane offsets (elements)
    const int l7 = lane & 7;
    const int lb3 = (lane >> 3) & 1;
    const int lb4 = lane >> 4;
    const int offA  = (wm * 32 + l7 + 8 * lb3) * AP + 8 * lb4;   // +im*16*AP, +ks*16
    const int offBT = (wn * 32 + l7 + 8 * lb4) * AP + 8 * lb3;   // +q*16*AP,  +ks*16
    const int offBN = (l7 + 8 * lb3) * BPN + wn * 32 + 8 * lb4;  // +q*16,     +ks*16*BPN

    const unsigned baseAh = (unsigned)__cvta_generic_to_shared(Ahs);
    const unsigned baseAl = (unsigned)__cvta_generic_to_shared(Als);
    const unsigned baseBh = (unsigned)__cvta_generic_to_shared(Bhs);
    const unsigned baseBl = (unsigned)__cvta_generic_to_shared(Bls);

    float acc[2][4][4];
#pragma unroll
    for (int im = 0; im < 2; im++)
#pragma unroll
        for (int in = 0; in < 4; in++)
#pragma unroll
            for (int q = 0; q < 4; q++) acc[im][in][q] = 0.f;

    const int niter = K >> 5;

#define MMAB(d, a, b0, b1)                                                    \
    asm volatile("mma.sync.aligned.m16n8k16.row.col.f32.bf16.bf16.f32 "       \
                 "{%0,%1,%2,%3}, {%4,%5,%6,%7}, {%8,%9}, {%0,%1,%2,%3};"      \
                 : "+f"(d[0]), "+f"(d[1]), "+f"(d[2]), "+f"(d[3])             \
                 : "r"(a[0]), "r"(a[1]), "r"(a[2]), "r"(a[3]), "r"(b0), "r"(b1))

    // ---- prologue: tile 0 ----
    {
#pragma unroll
        for (int i = 0; i < 2; i++) {
            int m = a_r + 64 * i;
            *(uint4*)&Ahs[m * AP + a_c8] = *(const uint4*)&Ah_g[(long)(m0 + m) * lda + a_c8];
            *(uint4*)&Als[m * AP + a_c8] = *(const uint4*)&Al_g[(long)(m0 + m) * lda + a_c8];
        }
        if (TRANSB) {
            *(uint4*)&Bhs[a_r * AP + a_c8] = *(const uint4*)&Bh_g[(long)(n0 + a_r) * ldb + a_c8];
            *(uint4*)&Bls[a_r * AP + a_c8] = *(const uint4*)&Bl_g[(long)(n0 + a_r) * ldb + a_c8];
        } else {
            *(uint4*)&Bhs[b_kr * BPN + b_nc] = *(const uint4*)&Bh_g[(long)b_kr * ldb + n0 + b_nc];
            *(uint4*)&Bls[b_kr * BPN + b_nc] = *(const uint4*)&Bl_g[(long)b_kr * ldb + n0 + b_nc];
        }
    }
    __syncthreads();

    int buf = 0;
    for (int it = 0; it < niter; it++) {
        uint4 rah[2], ral[2], rbh, rbl;
        const bool more = (it + 1 < niter);
        if (more) {
            const int k0 = (it + 1) << 5;
#pragma unroll
            for (int i = 0; i < 2; i++) {
                int m = a_r + 64 * i;
                rah[i] = *(const uint4*)&Ah_g[(long)(m0 + m) * lda + k0 + a_c8];
                ral[i] = *(const uint4*)&Al_g[(long)(m0 + m) * lda + k0 + a_c8];
            }
            if (TRANSB) {
                rbh = *(const uint4*)&Bh_g[(long)(n0 + a_r) * ldb + k0 + a_c8];
                rbl = *(const uint4*)&Bl_g[(long)(n0 + a_r) * ldb + k0 + a_c8];
            } else {
                rbh = *(const uint4*)&Bh_g[(long)(k0 + b_kr) * ldb + n0 + b_nc];
                rbl = *(const uint4*)&Bl_g[(long)(k0 + b_kr) * ldb + n0 + b_nc];
            }
        }

        const unsigned aH = baseAh + buf * (ASZ * 2);
        const unsigned aL = baseAl + buf * (ASZ * 2);
        const unsigned bH = baseBh + buf * (BSZ * 2);
        const unsigned bL = baseBl + buf * (BSZ * 2);
#pragma unroll
        for (int ks = 0; ks < 2; ks++) {
            unsigned ah[2][4], al4[2][4], bh[2][4], bl[2][4];
#pragma unroll
            for (int im = 0; im < 2; im++) {
                unsigned off = 2u * (offA + im * 16 * AP + ks * 16);
                ldsm4(aH + off, ah[im][0], ah[im][1], ah[im][2], ah[im][3]);
                ldsm4(aL + off, al4[im][0], al4[im][1], al4[im][2], al4[im][3]);
            }
#pragma unroll
            for (int q = 0; q < 2; q++) {
                if (TRANSB) {
                    unsigned off = 2u * (offBT + q * 16 * AP + ks * 16);
                    ldsm4(bH + off, bh[q][0], bh[q][1], bh[q][2], bh[q][3]);
                    ldsm4(bL + off, bl[q][0], bl[q][1], bl[q][2], bl[q][3]);
                } else {
                    unsigned off = 2u * (offBN + q * 16 + ks * 16 * BPN);
                    ldsm4t(bH + off, bh[q][0], bh[q][1], bh[q][2], bh[q][3]);
                    ldsm4t(bL + off, bl[q][0], bl[q][1], bl[q][2], bl[q][3]);
                }
            }
#pragma unroll
            for (int im = 0; im < 2; im++)
#pragma unroll
                for (int in = 0; in < 4; in++) {
                    int q = in >> 1, p = (in & 1) * 2;
                    MMAB(acc[im][in], al4[im], bh[q][p], bh[q][p + 1]);
                    MMAB(acc[im][in], ah[im],  bl[q][p], bl[q][p + 1]);
                    MMAB(acc[im][in], ah[im],  bh[q][p], bh[q][p + 1]);
                }
        }

        if (more) {
            int nb = buf ^ 1;
#pragma unroll
            for (int i = 0; i < 2; i++) {
                int m = a_r + 64 * i;
                *(uint4*)&Ahs[nb * ASZ + m * AP + a_c8] = rah[i];
                *(uint4*)&Als[nb * ASZ + m * AP + a_c8] = ral[i];
            }
            if (TRANSB) {
                *(uint4*)&Bhs[nb * BSZ + a_r * AP + a_c8] = rbh;
                *(uint4*)&Bls[nb * BSZ + a_r * AP + a_c8] = rbl;
            } else {
                *(uint4*)&Bhs[nb * BSZ + b_kr * BPN + b_nc] = rbh;
                *(uint4*)&Bls[nb * BSZ + b_kr * BPN + b_nc] = rbl;
            }
        }
        __syncthreads();
        buf ^= 1;
    }

    float scv = SCALE ? scale[z1] : 1.f;
    float* Cp = C + offC_g;
    __nv_bfloat16* CHp = CH + offC_g;
    __nv_bfloat16* CLp = CL + offC_g;
#pragma unroll
    for (int im = 0; im < 2; im++) {
        int r0 = m0 + wm * 32 + im * 16 + g;
        int r1 = r0 + 8;
#pragma unroll
        for (int in = 0; in < 4; in++) {
            int c = n0 + wn * 32 + in * 8 + 2 * tg;
            float b0 = 0.f, b1v = 0.f;
            if (BIAS) { b0 = bias[c]; b1v = bias[c + 1]; }
            float2 v0, v1;
            if (SCALE) {
                v0 = make_float2(acc[im][in][0] * scv, acc[im][in][1] * scv);
                v1 = make_float2(acc[im][in][2] * scv, acc[im][in][3] * scv);
            } else {
                v0 = make_float2(acc[im][in][0] + b0, acc[im][in][1] + b1v);
                v1 = make_float2(acc[im][in][2] + b0, acc[im][in][3] + b1v);
            }
            if (WF32) {
                *(float2*)&Cp[(long)r0 * ldc + c] = v0;
                *(float2*)&Cp[(long)r1 * ldc + c] = v1;
            }
            if (WHL) {
                __nv_bfloat162 h0 = __floats2bfloat162_rn(v0.x, v0.y);
                __nv_bfloat162 h1 = __floats2bfloat162_rn(v1.x, v1.y);
                float2 f0 = __bfloat1622float2(h0);
                float2 f1 = __bfloat1622float2(h1);
                __nv_bfloat162 l0 = __floats2bfloat162_rn(v0.x - f0.x, v0.y - f0.y);
                __nv_bfloat162 l1 = __floats2bfloat162_rn(v1.x - f1.x, v1.y - f1.y);
                *reinterpret_cast<__nv_bfloat162*>(&CHp[(long)r0 * ldc + c]) = h0;
                *reinterpret_cast<__nv_bfloat162*>(&CHp[(long)r1 * ldc + c]) = h1;
                *reinterpret_cast<__nv_bfloat162*>(&CLp[(long)r0 * ldc + c]) = l0;
                *reinterpret_cast<__nv_bfloat162*>(&CLp[(long)r1 * ldc + c]) = l1;
            }
        }
    }
#undef MMAB
}

// ---------------- init ----------------
__global__ void init_kernel()
{
    int idx = blockIdx.x * 1024 + threadIdx.x;   // 128 x 1024
    int b = idx >> 16, bin = idx & 65535;
    g_h16[b][bin] = 0u;
    if (idx < BB) g_mxu[idx] = 0u;
    if (idx < BB * HEADS) g_sjmx[idx] = 0u;
}

// ---------------- s_i, s_j + per-(b,h) max of s_j ----------------
__global__ void sij_kernel(const float* __restrict__ attn)
{
    int gw = (blockIdx.x * blockDim.x + threadIdx.x) >> 5;
    int lane = threadIdx.x & 31;
    if (gw >= BB * HEADS * NN_NODES) return;
    int b = gw / (HEADS * NN_NODES);
    int r = gw % (HEADS * NN_NODES);
    int h = r / NN_NODES;
    int n = r % NN_NODES;
    const float* hp = g_hp + ((long)(b * NN_NODES + n)) * FDIM + h * DH;
    const float* ai = attn + h * 2 * DH;
    float si = 0.f, sj = 0.f;
#pragma unroll
    for (int d = lane; d < DH; d += 32) {
        float v = hp[d];
        si += v * ai[d];
        sj += v * ai[DH + d];
    }
#pragma unroll
    for (int o = 16; o > 0; o >>= 1) {
        si += __shfl_down_sync(0xffffffffu, si, o);
        sj += __shfl_down_sync(0xffffffffu, sj, o);
    }
    if (lane == 0) {
        g_si[gw] = si;
        g_sj[gw] = sj;
        atomicMax(&g_sjmx[b * HEADS + h], enc_f(sj));
    }
}

// ---------------- attention softmax rows -> alpha planes ----------------
__global__ void alpha_kernel()
{
    __shared__ float sj[NN_NODES];
    int bh = blockIdx.y;
    int tid = threadIdx.x;
    for (int j = tid; j < NN_NODES; j += 256) sj[j] = g_sj[bh * NN_NODES + j];
    __syncthreads();

    int wrp = tid >> 5, lane = tid & 31;
    int i = blockIdx.x * 8 + wrp;
    float si = g_si[bh * NN_NODES + i];
    float sjmax = dec_f(g_sjmx[bh]);
    float M = si + sjmax;
    M = (M >= 0.f) ? M : 0.2f * M;
    float p[16];
    float sum = 0.f;
#pragma unroll
    for (int t = 0; t < 16; t++) {
        float e = si + sj[lane + 32 * t];
        e = (e >= 0.f) ? e : 0.2f * e;
        p[t] = expf(e - M);
        sum += p[t];
    }
#pragma unroll
    for (int o = 16; o > 0; o >>= 1) sum += __shfl_xor_sync(0xffffffffu, sum, o);
    float inv = 1.0f / sum;
    long base = (long)bh * NN2 + (long)i * NN_NODES;
    __nv_bfloat16* H = g_bf + O_ALH + base;
    __nv_bfloat16* L = g_bf + O_ALL + base;
#pragma unroll
    for (int t = 0; t < 16; t++) {
        float v = p[t] * inv;
        __nv_bfloat16 h, l;
        splitw(v, h, l);
        H[lane + 32 * t] = h;
        L[lane + 32 * t] = l;
    }
}

// ---------------- edge MLP scores + global max ----------------
__global__ void edge_kernel(const float* __restrict__ b1,
                            const float* __restrict__ w2,
                            const float* __restrict__ b2p)
{
    __shared__ float spi[16][260];
    __shared__ float spj[16][260];
    __shared__ float sw2[AH];
    __shared__ float red[256];
    int b = blockIdx.z;
    int i0 = blockIdx.y * 16, j0 = blockIdx.x * 16;
    int tid = threadIdx.x;

    float b1v = b1[tid];
    sw2[tid] = w2[tid];
#pragma unroll
    for (int l = 0; l < 16; l++) {
        spi[l][tid] = g_pij[((long)(b * NN_NODES) + i0 + l) * AH + tid] + b1v;
        spj[l][tid] = g_pij[PJOFF + ((long)(b * NN_NODES) + j0 + l) * AH + tid];
    }
    __syncthreads();
    int ti = tid >> 4, tj = tid & 15;
    float acc = 0.f;
#pragma unroll
    for (int a = 0; a < AH; a += 4) {
        float4 p4 = *(const float4*)&spi[ti][a];
        float4 q4 = *(const float4*)&spj[tj][a];
        float4 w4 = *(const float4*)&sw2[a];
        acc += fmaxf(p4.x + q4.x, 0.f) * w4.x;
        acc += fmaxf(p4.y + q4.y, 0.f) * w4.y;
        acc += fmaxf(p4.z + q4.z, 0.f) * w4.z;
        acc += fmaxf(p4.w + q4.w, 0.f) * w4.w;
    }
    float sc = (acc + b2p[0]) * 2.0f;   // /TEMP
    g_sc[(long)b * NN2 + (long)(i0 + ti) * NN_NODES + (j0 + tj)] = sc;

    red[tid] = sc;
    __syncthreads();
    for (int s = 128; s > 0; s >>= 1) {
        if (tid < s) red[tid] = fmaxf(red[tid], red[tid + s]);
        __syncthreads();
    }
    if (tid == 0) atomicMax(&g_mxu[b], enc_f(red[0]));
}

// ---------------- 2-level radix select on encoded scores ----------------
__global__ void histA_kernel()
{
    int b = blockIdx.y, blk = blockIdx.x, tid = threadIdx.x;
    const float* sm = g_sc + (long)b * NN2;
    for (int i = blk * 256 + tid; i < NN2; i += 32 * 256) {
        unsigned e = enc_f(sm[i]);
        atomicAdd(&g_h16[b][e >> 16], 1u);
    }
}
__global__ void histB_kernel()
{
    int b = blockIdx.y, blk = blockIdx.x, tid = threadIdx.x;
    unsigned hi = g_hi16[b];
    const float* sm = g_sc + (long)b * NN2;
    for (int i = blk * 256 + tid; i < NN2; i += 32 * 256) {
        unsigned e = enc_f(sm[i]);
        if ((e >> 16) == hi) atomicAdd(&g_h16[b][e & 0xFFFFu], 1u);
    }
}
__global__ void pick_kernel(int phase)
{
    __shared__ unsigned part[1024];
    __shared__ unsigned wsum[32];
    __shared__ int s_warp, s_thread;
    __shared__ unsigned s_base, s_base2;
    int b = blockIdx.x, tid = threadIdx.x, lane = tid & 31, wrp = tid >> 5;
    unsigned* bins = g_h16[b];
    unsigned rank = (phase == 0) ? (unsigned)THR_IDX : (unsigned)g_selrank[b];

    unsigned s = 0;
#pragma unroll 8
    for (int t = 0; t < 64; t++) s += bins[tid * 64 + t];
    part[tid] = s;
    unsigned wsv = s;
#pragma unroll
    for (int o = 16; o > 0; o >>= 1) wsv += __shfl_down_sync(0xffffffffu, wsv, o);
    if (lane == 0) wsum[wrp] = wsv;
    __syncthreads();

    if (tid == 0) {
        unsigned cum = 0; int w = 0;
        for (; w < 32; w++) { if (cum + wsum[w] > rank) break; cum += wsum[w]; }
        s_warp = w; s_base = cum;
    }
    __syncthreads();
    if (tid == s_warp * 32) {
        unsigned cum = s_base; int t = s_warp * 32;
        for (;; t++) { if (cum + part[t] > rank) break; cum += part[t]; }
        s_thread = t; s_base2 = cum;
    }
    __syncthreads();
    if (tid == s_thread) {
        unsigned cum = s_base2; int bin = tid * 64;
        for (;; bin++) { if (cum + bins[bin] > rank) break; cum += bins[bin]; }
        if (phase == 0) { g_hi16[b] = (unsigned)bin; g_selrank[b] = (int)(rank - cum); }
        else g_thrE[b] = (g_hi16[b] << 16) | (unsigned)bin;
    }
    __syncthreads();
    if (phase == 0) {
#pragma unroll 8
        for (int t = 0; t < 64; t++) bins[tid * 64 + t] = 0u;
    }
}

// ---------------- threshold + exp -> adj planes + partial sum ----------------
__global__ void thresh_kernel()
{
    int b = blockIdx.y, blk = blockIdx.x, tid = threadIdx.x;
    const float* sm = g_sc + (long)b * NN2;
    __nv_bfloat16* H = g_bf + O_ADJH + (long)b * NN2;
    __nv_bfloat16* L = g_bf + O_ADJL + (long)b * NN2;
    float mx = dec_f(g_mxu[b]);
    unsigned thr = g_thrE[b];
    float s = 0.f;
    for (int i = blk * 256 + tid; i < NN2; i += 64 * 256) {
        float v = sm[i];
        unsigned e = enc_f(v);
        float keep = (e >= thr) ? expf(v - mx) : 0.f;
        __nv_bfloat16 h, l;
        splitw(keep, h, l);
        H[i] = h; L[i] = l;
        s += keep;
    }
    __shared__ float sh[256];
    sh[tid] = s; __syncthreads();
    for (int q = 128; q > 0; q >>= 1) { if (tid < q) sh[tid] += sh[tid + q]; __syncthreads(); }
    if (tid == 0) g_part[b * 64 + blk] = sh[0];
}
__global__ void inv_kernel()
{
    __shared__ float sh[64];
    int b = blockIdx.x, tid = threadIdx.x;
    sh[tid] = g_part[b * 64 + tid];
    __syncthreads();
    for (int q = 32; q > 0; q >>= 1) { if (tid < q) sh[tid] += sh[tid + q]; __syncthreads(); }
    if (tid == 0) g_inv[b] = 1.0f / sh[0];
}

// ---------------- batchnorm + relu ----------------
template<bool WHL>
__global__ void bn_relu_kernel(float* __restrict__ h,
                               const float* __restrict__ ga,
                               const float* __restrict__ be, int C,
                               __nv_bfloat16* __restrict__ Hout,
                               __nv_bfloat16* __restrict__ Lout)
{
    __shared__ float sh[8][32], sh2[8][32];
    int c = blockIdx.x * 32 + threadIdx.x;
    int ry = threadIdx.y;
    float s = 0.f, s2 = 0.f;
    for (int r = ry; r < BN_M; r += 8) {
        float v = h[(long)r * C + c];
        s += v; s2 += v * v;
    }
    sh[ry][threadIdx.x] = s; sh2[ry][threadIdx.x] = s2;
    __syncthreads();
    if (ry == 0) {
        for (int r = 1; r < 8; r++) { s += sh[r][threadIdx.x]; s2 += sh2[r][threadIdx.x]; }
        float m = s / (float)BN_M;
        float v = s2 / (float)BN_M - m * m;
        sh[0][threadIdx.x] = m;
        sh2[0][threadIdx.x] = rsqrtf(v + 1e-5f);
    }
    __syncthreads();
    float m = sh[0][threadIdx.x], inv = sh2[0][threadIdx.x];
    float gg = ga[c], bb = be[c];
    for (int r = ry; r < BN_M; r += 8) {
        float v = h[(long)r * C + c];
        float y = fmaxf((v - m) * inv * gg + bb, 0.f);
        if (WHL) {
            __nv_bfloat16 hh, ll;
            splitw(y, hh, ll);
            Hout[(long)r * C + c] = hh;
            Lout[(long)r * C + c] = ll;
        } else {
            h[(long)r * C + c] = y;
        }
    }
}

// ---------------- mean pool + classifier ----------------
__global__ void head_kernel(const float* __restrict__ cls_w,
                            const float* __restrict__ cls_b,
                            float* __restrict__ out)
{
    __shared__ float acc4[4][OUTF];
    __shared__ float feat[OUTF];
    int b = blockIdx.x, tid = threadIdx.x; // 512 threads
    int r0 = tid >> 7, f = tid & 127;
    float s = 0.f;
    for (int r = r0; r < NN_NODES; r += 4)
        s += g_h2b[((long)b * NN_NODES + r) * OUTF + f];
    acc4[r0][f] = s;
    __syncthreads();
    if (tid < OUTF)
        feat[tid] = (acc4[0][tid] + acc4[1][tid] + acc4[2][tid] + acc4[3][tid]) / (float)NN_NODES;
    __syncthreads();
    if (tid < NCLS) {
        float acc = cls_b[tid];
        for (int ff = 0; ff < OUTF; ff++) acc += feat[ff] * cls_w[tid * OUTF + ff];
        out[b * NCLS + tid] = acc;
    }
}

// ---------------- launcher ----------------
extern "C" void kernel_launch(void* const* d_in, const int* in_sizes, int n_in,
                              void* d_out, int out_size)
{
    const float* x     = (const float*)d_in[0];
    const float* Wg    = (const float*)d_in[1];
    const float* attn  = (const float*)d_in[2];
    const float* W1    = (const float*)d_in[3];
    const float* b1    = (const float*)d_in[4];
    const float* w2    = (const float*)d_in[5];
    const float* b2    = (const float*)d_in[6];
    const float* gc1_w = (const float*)d_in[7];
    const float* gc1_b = (const float*)d_in[8];
    const float* bn1_g = (const float*)d_in[9];
    const float* bn1_b = (const float*)d_in[10];
    const float* gc2_w = (const float*)d_in[11];
    const float* gc2_b = (const float*)d_in[12];
    const float* bn2_g = (const float*)d_in[13];
    const float* bn2_b = (const float*)d_in[14];
    const float* cls_w = (const float*)d_in[15];
    const float* cls_b = (const float*)d_in[16];
    float* out = (float*)d_out;

    float *hp, *pij, *h1b, *h2b, *ginv;
    __nv_bfloat16* bf;
    cudaGetSymbolAddress((void**)&hp,  g_hp);
    cudaGetSymbolAddress((void**)&pij, g_pij);
    cudaGetSymbolAddress((void**)&h1b, g_h1b);
    cudaGetSymbolAddress((void**)&h2b, g_h2b);
    cudaGetSymbolAddress((void**)&ginv, g_inv);
    cudaGetSymbolAddress((void**)&bf, g_bf);

    __nv_bfloat16 *XH = bf + O_XH, *XL = bf + O_XL;
    __nv_bfloat16 *WGH = bf + O_WGH, *WGL = bf + O_WGL;
    __nv_bfloat16 *W1H = bf + O_W1H, *W1L = bf + O_W1L;
    __nv_bfloat16 *GC1H = bf + O_GC1H, *GC1L = bf + O_GC1L;
    __nv_bfloat16 *GC2H = bf + O_GC2H, *GC2L = bf + O_GC2L;
    __nv_bfloat16 *HPH = bf + O_HPH, *HPL = bf + O_HPL;
    __nv_bfloat16 *ALH = bf + O_ALH, *ALL_ = bf + O_ALL;
    __nv_bfloat16 *NFH = bf + O_NFH, *NFL = bf + O_NFL;
    __nv_bfloat16 *ADJH = bf + O_ADJH, *ADJL = bf + O_ADJL;
    __nv_bfloat16 *H1H = bf + O_H1H, *H1L = bf + O_H1L;
    __nv_bfloat16 *H1BH = bf + O_H1BH, *H1BL = bf + O_H1BL;
    __nv_bfloat16 *H2H = bf + O_H2H, *H2L = bf + O_H2L;

    const int SM = 61440;  // dynamic smem bytes for mma_gemm
    cudaFuncSetAttribute(mma_gemm<true,  false, false, true,  true >, cudaFuncAttributeMaxDynamicSharedMemorySize, SM);
    cudaFuncSetAttribute(mma_gemm<false, false, false, false, true >, cudaFuncAttributeMaxDynamicSharedMemorySize, SM);
    cudaFuncSetAttribute(mma_gemm<true,  false, false, true,  false>, cudaFuncAttributeMaxDynamicSharedMemorySize, SM);
    cudaFuncSetAttribute(mma_gemm<false, false, true,  false, true >, cudaFuncAttributeMaxDynamicSharedMemorySize, SM);
    cudaFuncSetAttribute(mma_gemm<true,  true,  false, true,  false>, cudaFuncAttributeMaxDynamicSharedMemorySize, SM);

    init_kernel<<<128, 1024>>>();

    // 0) convert inputs to bf16 hi/lo planes
    conv_kernel<<<SZ_X/4/256, 256>>>(x, XH, XL, SZ_X/4);
    conv_kernel<<<SZ_WG/4/256, 256>>>(Wg, WGH, WGL, SZ_WG/4);
    conv_kernel<<<SZ_W1/4/256, 256>>>(W1, W1H, W1L, SZ_W1/4);
    conv_kernel<<<SZ_GC1/4/256, 256>>>(gc1_w, GC1H, GC1L, SZ_GC1/4);
    conv_kernel<<<SZ_GC2/4/256, 256>>>(gc2_w, GC2H, GC2L, SZ_GC2/4);

    // 1) hp = x @ Wg^T  -> fp32 + planes
    mma_gemm<true, false, false, true, true><<<dim3(16, 8, 1), 256, SM>>>(
        XH, XL, FDIM, WGH, WGL, FDIM, 0, 0, 0, 0, nullptr, nullptr,
        hp, HPH, HPL, FDIM, 0, 0, FDIM, 1);

    // 2) s_i, s_j + sjmax
    sij_kernel<<<(BB * HEADS * NN_NODES * 32 + 255) / 256, 256>>>(attn);

    // 3a) softmax rows -> alpha planes
    alpha_kernel<<<dim3(NN_NODES / 8, BB * HEADS), 256>>>();

    // 3b) nf = alpha @ hp (per b,h) -> planes only
    mma_gemm<false, false, false, false, true><<<dim3(DH / 64, NN_NODES / 128, BB * HEADS), 256, SM>>>(
        ALH, ALL_, NN_NODES, HPH, HPL, FDIM,
        (long)HEADS * NN2, (long)NN2, (long)NN_NODES * FDIM, (long)DH,
        nullptr, nullptr, nullptr, NFH, NFL, FDIM,
        (long)NN_NODES * FDIM, (long)DH, NN_NODES, HEADS);

    // 4) pi/pj fused -> fp32
    mma_gemm<true, false, false, true, false><<<dim3(AH / 64, 8, 2), 256, SM>>>(
        NFH, NFL, FDIM, W1H, W1L, 2 * FDIM,
        0, 0, FDIM, 0, nullptr, nullptr,
        pij, nullptr, nullptr, AH, (long)PJOFF, 0, FDIM, 1);

    // 5) edge scores + global max
    edge_kernel<<<dim3(NN_NODES / 16, NN_NODES / 16, BB), 256>>>(b1, w2, b2);

    // 6) exact k-th order statistic (2-level 16-bit radix)
    histA_kernel<<<dim3(32, BB), 256>>>();
    pick_kernel<<<BB, 1024>>>(0);
    histB_kernel<<<dim3(32, BB), 256>>>();
    pick_kernel<<<BB, 1024>>>(1);

    // 7) threshold + exp -> adj planes; sum -> 1/denom
    thresh_kernel<<<dim3(64, BB), 256>>>();
    inv_kernel<<<BB, 64>>>();

    // 8) h1 = (adjU @ nf) * inv[b] -> planes
    mma_gemm<false, false, true, false, true><<<dim3(FDIM / 64, NN_NODES / 128, BB), 256, SM>>>(
        ADJH, ADJL, NN_NODES, NFH, NFL, FDIM,
        (long)NN2, 0, (long)NN_NODES * FDIM, 0,
        nullptr, ginv, nullptr, H1H, H1L, FDIM,
        (long)NN_NODES * FDIM, 0, NN_NODES, 1);

    // 9) h1b = h1 @ gc1_w^T + gc1_b -> fp32
    mma_gemm<true, true, false, true, false><<<dim3(HID / 64, 8, 1), 256, SM>>>(
        H1H, H1L, FDIM, GC1H, GC1L, FDIM,
        0, 0, 0, 0, gc1_b, nullptr,
        h1b, nullptr, nullptr, HID, 0, 0, FDIM, 1);

    // 10) bn1 + relu -> planes
    bn_relu_kernel<true><<<HID / 32, dim3(32, 8)>>>(h1b, bn1_g, bn1_b, HID, H1BH, H1BL);

    // 11) h2 = (adjU @ h1b) * inv[b] -> planes
    mma_gemm<false, false, true, false, true><<<dim3(HID / 64, NN_NODES / 128, BB), 256, SM>>>(
        ADJH, ADJL, NN_NODES, H1BH, H1BL, HID,
        (long)NN2, 0, (long)NN_NODES * HID, 0,
        nullptr, ginv, nullptr, H2H, H2L, HID,
        (long)NN_NODES * HID, 0, NN_NODES, 1);

    // 12) h2b = h2 @ gc2_w^T + gc2_b -> fp32
    mma_gemm<true, true, false, true, false><<<dim3(OUTF / 64, 8, 1), 256, SM>>>(
        H2H, H2L, HID, GC2H, GC2L, HID,
        0, 0, 0, 0, gc2_b, nullptr,
        h2b, nullptr, nullptr, OUTF, 0, 0, HID, 1);

    // 13) bn2 + relu (in place fp32)
    bn_relu_kernel<false><<<OUTF / 32, dim3(32, 8)>>>(h2b, bn2_g, bn2_b, OUTF, nullptr, nullptr);

    // 14) mean pool + classifier
    head_kernel<<<BB, 512>>>(cls_w, cls_b, out);
}

// round 13
// speedup vs baseline: 1.1167x; 1.1167x over previous
#include <cuda_runtime.h>
#include <cuda_bf16.h>
#include <math.h>

// ---------------- problem constants ----------------
#define BB 2
#define NN_NODES 512
#define FDIM 1024
#define HEADS 4
#define DH 256
#define AH 256
#define HID 512
#define OUTF 128
#define NCLS 10
#define NN2 (NN_NODES*NN_NODES)          // 262144
#define KSEL 209715                       // int(0.8 * N*N)
#define THR_IDX (NN2 - KSEL)              // 52429
#define BN_M (BB*NN_NODES)
#define PJOFF (BB*NN_NODES*AH)

// ---------------- fp32 scratch ----------------
__device__ float g_hp [BB*NN_NODES*FDIM];
__device__ float g_si [BB*HEADS*NN_NODES];
__device__ float g_sj [BB*HEADS*NN_NODES];
__device__ float g_pij[2*BB*NN_NODES*AH];
__device__ float g_sc [BB*NN2];
__device__ float g_h1b[BB*NN_NODES*HID];
__device__ float g_h2b[BB*NN_NODES*OUTF];
__device__ float g_part[BB*64];
__device__ float g_inv[BB];
__device__ unsigned g_mxu[BB];
__device__ unsigned g_sjmx[BB*HEADS];
__device__ unsigned g_h16[BB][65536];
__device__ unsigned g_hi16[BB];
__device__ int g_selrank[BB];
__device__ unsigned g_thrE[BB];

// ---------------- bf16 hi/lo plane arena ----------------
#define SZ_X    (BB*NN_NODES*FDIM)
#define SZ_WG   (FDIM*FDIM)
#define SZ_W1   (AH*2*FDIM)
#define SZ_GC1  (HID*FDIM)
#define SZ_GC2  (OUTF*HID)
#define SZ_HP   (BB*NN_NODES*FDIM)
#define SZ_AL   (BB*HEADS*NN2)
#define SZ_NF   (BB*NN_NODES*FDIM)
#define SZ_ADJ  (BB*NN2)
#define SZ_H1   (BB*NN_NODES*FDIM)
#define SZ_H1B  (BB*NN_NODES*HID)
#define SZ_H2   (BB*NN_NODES*HID)

#define O_XH   ((size_t)0)
#define O_XL   (O_XH   + SZ_X)
#define O_WGH  (O_XL   + SZ_X)
#define O_WGL  (O_WGH  + SZ_WG)
#define O_W1H  (O_WGL  + SZ_WG)
#define O_W1L  (O_W1H  + SZ_W1)
#define O_GC1H (O_W1L  + SZ_W1)
#define O_GC1L (O_GC1H + SZ_GC1)
#define O_GC2H (O_GC1L + SZ_GC1)
#define O_GC2L (O_GC2H + SZ_GC2)
#define O_HPH  (O_GC2L + SZ_GC2)
#define O_HPL  (O_HPH  + SZ_HP)
#define O_ALH  (O_HPL  + SZ_HP)
#define O_ALL  (O_ALH  + SZ_AL)
#define O_NFH  (O_ALL  + SZ_AL)
#define O_NFL  (O_NFH  + SZ_NF)
#define O_ADJH (O_NFL  + SZ_NF)
#define O_ADJL (O_ADJH + SZ_ADJ)
#define O_H1H  (O_ADJL + SZ_ADJ)
#define O_H1L  (O_H1H  + SZ_H1)
#define O_H1BH (O_H1L  + SZ_H1)
#define O_H1BL (O_H1BH + SZ_H1B)
#define O_H2H  (O_H1BL + SZ_H1B)
#define O_H2L  (O_H2H  + SZ_H2)
#define O_END  (O_H2L  + SZ_H2)

__device__ __nv_bfloat16 g_bf[O_END];

// ---------------- helpers ----------------
__device__ __forceinline__ unsigned enc_f(float f) {
    unsigned u = __float_as_uint(f);
    return (u & 0x80000000u) ? ~u : (u | 0x80000000u);
}
__device__ __forceinline__ float dec_f(unsigned e) {
    unsigned u = (e & 0x80000000u) ? (e ^ 0x80000000u) : ~e;
    return __uint_as_float(u);
}
__device__ __forceinline__ void splitw(float v, __nv_bfloat16& h, __nv_bfloat16& l) {
    h = __float2bfloat16_rn(v);
    l = __float2bfloat16_rn(v - __bfloat162float(h));
}

__device__ __forceinline__ void ldsm4(unsigned addr, unsigned& r0, unsigned& r1,
                                      unsigned& r2, unsigned& r3)
{
    asm volatile("ldmatrix.sync.aligned.m8n8.x4.shared.b16 {%0,%1,%2,%3}, [%4];"
                 : "=r"(r0), "=r"(r1), "=r"(r2), "=r"(r3) : "r"(addr));
}
__device__ __forceinline__ void ldsm4t(unsigned addr, unsigned& r0, unsigned& r1,
                                       unsigned& r2, unsigned& r3)
{
    asm volatile("ldmatrix.sync.aligned.m8n8.x4.trans.shared.b16 {%0,%1,%2,%3}, [%4];"
                 : "=r"(r0), "=r"(r1), "=r"(r2), "=r"(r3) : "r"(addr));
}

// ---------------- fused init + all f32->bf16 plane conversions ----------------
#define Q_X   (SZ_X/4)
#define Q_WG  (SZ_WG/4)
#define Q_W1  (SZ_W1/4)
#define Q_GC1 (SZ_GC1/4)
#define Q_GC2 (SZ_GC2/4)
#define Q_TOT (Q_X+Q_WG+Q_W1+Q_GC1+Q_GC2)   // 704768
__global__ void initconv_kernel(const float* __restrict__ x,
                                const float* __restrict__ wg,
                                const float* __restrict__ w1,
                                const float* __restrict__ gc1,
                                const float* __restrict__ gc2)
{
    int q = blockIdx.x * 256 + threadIdx.x;
    if (q < BB * 65536) {
        ((unsigned*)g_h16)[q] = 0u;
        if (q < BB) g_mxu[q] = 0u;
        if (q < BB * HEADS) g_sjmx[q] = 0u;
    }
    if (q >= Q_TOT) return;
    const float* src; __nv_bfloat16 *H, *L; int lq = q;
    if (lq < Q_X)        { src = x;   H = g_bf + O_XH;   L = g_bf + O_XL; }
    else if ((lq -= Q_X)   < Q_WG)  { src = wg;  H = g_bf + O_WGH;  L = g_bf + O_WGL; }
    else if ((lq -= Q_WG)  < Q_W1)  { src = w1;  H = g_bf + O_W1H;  L = g_bf + O_W1L; }
    else if ((lq -= Q_W1)  < Q_GC1) { src = gc1; H = g_bf + O_GC1H; L = g_bf + O_GC1L; }
    else { lq -= Q_GC1;               src = gc2; H = g_bf + O_GC2H; L = g_bf + O_GC2L; }
    float4 v = ((const float4*)src)[lq];
    __nv_bfloat162 h0 = __floats2bfloat162_rn(v.x, v.y);
    __nv_bfloat162 h1 = __floats2bfloat162_rn(v.z, v.w);
    float2 f0 = __bfloat1622float2(h0);
    float2 f1 = __bfloat1622float2(h1);
    __nv_bfloat162 l0 = __floats2bfloat162_rn(v.x - f0.x, v.y - f0.y);
    __nv_bfloat162 l1 = __floats2bfloat162_rn(v.z - f1.x, v.w - f1.y);
    *reinterpret_cast<__nv_bfloat162*>(H + 4*lq)     = h0;
    *reinterpret_cast<__nv_bfloat162*>(H + 4*lq + 2) = h1;
    *reinterpret_cast<__nv_bfloat162*>(L + 4*lq)     = l0;
    *reinterpret_cast<__nv_bfloat162*>(L + 4*lq + 2) = l1;
}

// ---------------- bf16 split-operand tensor-core GEMM ----------------
// BM=64, BN=64, 128 threads, warp tile 32x32, K-tile 32, double-buffered.
// Operands are pre-split hi/lo planes.
#define AP  40
#define BPN 72
#define PSZ 2560   // elems per plane-buffer
template<bool TRANSB, bool BIAS, bool SCALE, bool WF32, bool WHL>
__global__ void __launch_bounds__(128) mma_gemm(
    const __nv_bfloat16* __restrict__ AH_, const __nv_bfloat16* __restrict__ AL_, int lda,
    const __nv_bfloat16* __restrict__ BH_, const __nv_bfloat16* __restrict__ BL_, int ldb,
    long sA, long sA2, long sB, long sB2,
    const float* __restrict__ bias, const float* __restrict__ scale,
    float* __restrict__ C, __nv_bfloat16* __restrict__ CH, __nv_bfloat16* __restrict__ CL,
    int ldc, long sC, long sC2, int K, int zdiv)
{
    __shared__ __align__(16) __nv_bfloat16 Ahs[2][PSZ];
    __shared__ __align__(16) __nv_bfloat16 Als[2][PSZ];
    __shared__ __align__(16) __nv_bfloat16 Bhs[2][PSZ];
    __shared__ __align__(16) __nv_bfloat16 Bls[2][PSZ];

    const int bz = blockIdx.z;
    const int z1 = bz / zdiv, z2 = bz % zdiv;
    const long offA_g = z1 * sA + z2 * sA2;
    const long offB_g = z1 * sB + z2 * sB2;
    const long offC_g = z1 * sC + z2 * sC2;
    const __nv_bfloat16* Ah_g = AH_ + offA_g;
    const __nv_bfloat16* Al_g = AL_ + offA_g;
    const __nv_bfloat16* Bh_g = BH_ + offB_g;
    const __nv_bfloat16* Bl_g = BL_ + offB_g;

    const int m0 = blockIdx.y * 64;
    const int n0 = blockIdx.x * 64;
    const int tid = threadIdx.x;
    const int lane = tid & 31;
    const int wid  = tid >> 5;
    const int wm = wid >> 1, wn = wid & 1;
    const int g  = lane >> 2;
    const int tg = lane & 3;

    // staging: A/TRANSB-B: 64 rows x 32 k -> row=tid>>2 (0..31)+32i, chunk (tid&3)*8
    const int a_r = tid >> 2;           // 0..31
    const int a_c8 = (tid & 3) * 8;
    // !TRANSB B: 32 k-rows x 64 n -> row=tid>>3 (0..15)+16i, chunk (tid&7)*8
    const int b_kr = tid >> 3;          // 0..15
    const int b_nc = (tid & 7) * 8;

    const int l7 = lane & 7;
    const int lb3 = (lane >> 3) & 1;
    const int lb4 = lane >> 4;
    const int offA  = (wm * 32 + l7 + 8 * lb3) * AP + 8 * lb4;
    const int offBT = (wn * 32 + l7 + 8 * lb4) * AP + 8 * lb3;
    const int offBN = (l7 + 8 * lb3) * BPN + wn * 32 + 8 * lb4;

    const unsigned baseAh = (unsigned)__cvta_generic_to_shared(&Ahs[0][0]);
    const unsigned baseAl = (unsigned)__cvta_generic_to_shared(&Als[0][0]);
    const unsigned baseBh = (unsigned)__cvta_generic_to_shared(&Bhs[0][0]);
    const unsigned baseBl = (unsigned)__cvta_generic_to_shared(&Bls[0][0]);

    float acc[2][4][4];
#pragma unroll
    for (int im = 0; im < 2; im++)
#pragma unroll
        for (int in = 0; in < 4; in++)
#pragma unroll
            for (int q = 0; q < 4; q++) acc[im][in][q] = 0.f;

    const int niter = K >> 5;

#define MMAB(d, a, b0, b1)                                                    \
    asm volatile("mma.sync.aligned.m16n8k16.row.col.f32.bf16.bf16.f32 "       \
                 "{%0,%1,%2,%3}, {%4,%5,%6,%7}, {%8,%9}, {%0,%1,%2,%3};"      \
                 : "+f"(d[0]), "+f"(d[1]), "+f"(d[2]), "+f"(d[3])             \
                 : "r"(a[0]), "r"(a[1]), "r"(a[2]), "r"(a[3]), "r"(b0), "r"(b1))

    // ---- prologue: tile 0 ----
    {
#pragma unroll
        for (int i = 0; i < 2; i++) {
            int m = a_r + 32 * i;
            *(uint4*)&Ahs[0][m * AP + a_c8] = *(const uint4*)&Ah_g[(long)(m0 + m) * lda + a_c8];
            *(uint4*)&Als[0][m * AP + a_c8] = *(const uint4*)&Al_g[(long)(m0 + m) * lda + a_c8];
            if (TRANSB) {
                *(uint4*)&Bhs[0][m * AP + a_c8] = *(const uint4*)&Bh_g[(long)(n0 + m) * ldb + a_c8];
                *(uint4*)&Bls[0][m * AP + a_c8] = *(const uint4*)&Bl_g[(long)(n0 + m) * ldb + a_c8];
            } else {
                int kk = b_kr + 16 * i;
                *(uint4*)&Bhs[0][kk * BPN + b_nc] = *(const uint4*)&Bh_g[(long)kk * ldb + n0 + b_nc];
                *(uint4*)&Bls[0][kk * BPN + b_nc] = *(const uint4*)&Bl_g[(long)kk * ldb + n0 + b_nc];
            }
        }
    }
    __syncthreads();

    int buf = 0;
    for (int it = 0; it < niter; it++) {
        uint4 rah[2], ral[2], rbh[2], rbl[2];
        const bool more = (it + 1 < niter);
        if (more) {
            const int k0 = (it + 1) << 5;
#pragma unroll
            for (int i = 0; i < 2; i++) {
                int m = a_r + 32 * i;
                rah[i] = *(const uint4*)&Ah_g[(long)(m0 + m) * lda + k0 + a_c8];
                ral[i] = *(const uint4*)&Al_g[(long)(m0 + m) * lda + k0 + a_c8];
                if (TRANSB) {
                    rbh[i] = *(const uint4*)&Bh_g[(long)(n0 + m) * ldb + k0 + a_c8];
                    rbl[i] = *(const uint4*)&Bl_g[(long)(n0 + m) * ldb + k0 + a_c8];
                } else {
                    int kk = b_kr + 16 * i;
                    rbh[i] = *(const uint4*)&Bh_g[(long)(k0 + kk) * ldb + n0 + b_nc];
                    rbl[i] = *(const uint4*)&Bl_g[(long)(k0 + kk) * ldb + n0 + b_nc];
                }
            }
        }

        const unsigned aH = baseAh + buf * (PSZ * 2);
        const unsigned aL = baseAl + buf * (PSZ * 2);
        const unsigned bH = baseBh + buf * (PSZ * 2);
        const unsigned bL = baseBl + buf * (PSZ * 2);
#pragma unroll
        for (int ks = 0; ks < 2; ks++) {
            unsigned ah[2][4], al4[2][4], bh[2][4], bl[2][4];
#pragma unroll
            for (int im = 0; im < 2; im++) {
                unsigned off = 2u * (offA + im * 16 * AP + ks * 16);
                ldsm4(aH + off, ah[im][0], ah[im][1], ah[im][2], ah[im][3]);
                ldsm4(aL + off, al4[im][0], al4[im][1], al4[im][2], al4[im][3]);
            }
#pragma unroll
            for (int q = 0; q < 2; q++) {
                if (TRANSB) {
                    unsigned off = 2u * (offBT + q * 16 * AP + ks * 16);
                    ldsm4(bH + off, bh[q][0], bh[q][1], bh[q][2], bh[q][3]);
                    ldsm4(bL + off, bl[q][0], bl[q][1], bl[q][2], bl[q][3]);
                } else {
                    unsigned off = 2u * (offBN + q * 16 + ks * 16 * BPN);
                    ldsm4t(bH + off, bh[q][0], bh[q][1], bh[q][2], bh[q][3]);
                    ldsm4t(bL + off, bl[q][0], bl[q][1], bl[q][2], bl[q][3]);
                }
            }
#pragma unroll
            for (int im = 0; im < 2; im++)
#pragma unroll
                for (int in = 0; in < 4; in++) {
                    int q = in >> 1, p = (in & 1) * 2;
                    MMAB(acc[im][in], al4[im], bh[q][p], bh[q][p + 1]);
                    MMAB(acc[im][in], ah[im],  bl[q][p], bl[q][p + 1]);
                    MMAB(acc[im][in], ah[im],  bh[q][p], bh[q][p + 1]);
                }
        }

        if (more) {
            int nb = buf ^ 1;
#pragma unroll
            for (int i = 0; i < 2; i++) {
                int m = a_r + 32 * i;
                *(uint4*)&Ahs[nb][m * AP + a_c8] = rah[i];
                *(uint4*)&Als[nb][m * AP + a_c8] = ral[i];
                if (TRANSB) {
                    *(uint4*)&Bhs[nb][m * AP + a_c8] = rbh[i];
                    *(uint4*)&Bls[nb][m * AP + a_c8] = rbl[i];
                } else {
                    int kk = b_kr + 16 * i;
                    *(uint4*)&Bhs[nb][kk * BPN + b_nc] = rbh[i];
                    *(uint4*)&Bls[nb][kk * BPN + b_nc] = rbl[i];
                }
            }
        }
        __syncthreads();
        buf ^= 1;
    }

    float scv = SCALE ? scale[z1] : 1.f;
    float* Cp = C + offC_g;
    __nv_bfloat16* CHp = CH + offC_g;
    __nv_bfloat16* CLp = CL + offC_g;
#pragma unroll
    for (int im = 0; im < 2; im++) {
        int r0 = m0 + wm * 32 + im * 16 + g;
        int r1 = r0 + 8;
#pragma unroll
        for (int in = 0; in < 4; in++) {
            int c = n0 + wn * 32 + in * 8 + 2 * tg;
            float b0 = 0.f, b1v = 0.f;
            if (BIAS) { b0 = bias[c]; b1v = bias[c + 1]; }
            float2 v0, v1;
            if (SCALE) {
                v0 = make_float2(acc[im][in][0] * scv, acc[im][in][1] * scv);
                v1 = make_float2(acc[im][in][2] * scv, acc[im][in][3] * scv);
            } else {
                v0 = make_float2(acc[im][in][0] + b0, acc[im][in][1] + b1v);
                v1 = make_float2(acc[im][in][2] + b0, acc[im][in][3] + b1v);
            }
            if (WF32) {
                *(float2*)&Cp[(long)r0 * ldc + c] = v0;
                *(float2*)&Cp[(long)r1 * ldc + c] = v1;
            }
            if (WHL) {
                __nv_bfloat162 h0 = __floats2bfloat162_rn(v0.x, v0.y);
                __nv_bfloat162 h1 = __floats2bfloat162_rn(v1.x, v1.y);
                float2 f0 = __bfloat1622float2(h0);
                float2 f1 = __bfloat1622float2(h1);
                __nv_bfloat162 l0 = __floats2bfloat162_rn(v0.x - f0.x, v0.y - f0.y);
                __nv_bfloat162 l1 = __floats2bfloat162_rn(v1.x - f1.x, v1.y - f1.y);
                *reinterpret_cast<__nv_bfloat162*>(&CHp[(long)r0 * ldc + c]) = h0;
                *reinterpret_cast<__nv_bfloat162*>(&CHp[(long)r1 * ldc + c]) = h1;
                *reinterpret_cast<__nv_bfloat162*>(&CLp[(long)r0 * ldc + c]) = l0;
                *reinterpret_cast<__nv_bfloat162*>(&CLp[(long)r1 * ldc + c]) = l1;
            }
        }
    }
#undef MMAB
}

// ---------------- s_i, s_j + per-(b,h) max of s_j ----------------
__global__ void sij_kernel(const float* __restrict__ attn)
{
    int gw = (blockIdx.x * blockDim.x + threadIdx.x) >> 5;
    int lane = threadIdx.x & 31;
    if (gw >= BB * HEADS * NN_NODES) return;
    int b = gw / (HEADS * NN_NODES);
    int r = gw % (HEADS * NN_NODES);
    int h = r / NN_NODES;
    int n = r % NN_NODES;
    const float* hp = g_hp + ((long)(b * NN_NODES + n)) * FDIM + h * DH;
    const float* ai = attn + h * 2 * DH;
    float si = 0.f, sj = 0.f;
#pragma unroll
    for (int d = lane; d < DH; d += 32) {
        float v = hp[d];
        si += v * ai[d];
        sj += v * ai[DH + d];
    }
#pragma unroll
    for (int o = 16; o > 0; o >>= 1) {
        si += __shfl_down_sync(0xffffffffu, si, o);
        sj += __shfl_down_sync(0xffffffffu, sj, o);
    }
    if (lane == 0) {
        g_si[gw] = si;
        g_sj[gw] = sj;
        atomicMax(&g_sjmx[b * HEADS + h], enc_f(sj));
    }
}

// ---------------- attention softmax rows -> alpha planes ----------------
__global__ void alpha_kernel()
{
    __shared__ float sj[NN_NODES];
    int bh = blockIdx.y;
    int tid = threadIdx.x;
    for (int j = tid; j < NN_NODES; j += 256) sj[j] = g_sj[bh * NN_NODES + j];
    __syncthreads();

    int wrp = tid >> 5, lane = tid & 31;
    int i = blockIdx.x * 8 + wrp;
    float si = g_si[bh * NN_NODES + i];
    float sjmax = dec_f(g_sjmx[bh]);
    float M = si + sjmax;
    M = (M >= 0.f) ? M : 0.2f * M;
    float p[16];
    float sum = 0.f;
#pragma unroll
    for (int t = 0; t < 16; t++) {
        float e = si + sj[lane + 32 * t];
        e = (e >= 0.f) ? e : 0.2f * e;
        p[t] = expf(e - M);
        sum += p[t];
    }
#pragma unroll
    for (int o = 16; o > 0; o >>= 1) sum += __shfl_xor_sync(0xffffffffu, sum, o);
    float inv = 1.0f / sum;
    long base = (long)bh * NN2 + (long)i * NN_NODES;
    __nv_bfloat16* H = g_bf + O_ALH + base;
    __nv_bfloat16* L = g_bf + O_ALL + base;
#pragma unroll
    for (int t = 0; t < 16; t++) {
        float v = p[t] * inv;
        __nv_bfloat16 h, l;
        splitw(v, h, l);
        H[lane + 32 * t] = h;
        L[lane + 32 * t] = l;
    }
}

// ---------------- edge MLP: 64x64 edges/block, 4x4 per thread ----------------
// Also fuses: global max (atomicMax) + high-16 histogram (atomicAdd).
__global__ void __launch_bounds__(256) edge_kernel(
    const float* __restrict__ b1,
    const float* __restrict__ w2,
    const float* __restrict__ b2p)
{
    __shared__ float spi[64][36];
    __shared__ float spj[64][36];   // permuted rows: prow = ((j&3)<<4)|(j>>2)
    __shared__ float sw2[AH];
    __shared__ float red[256];
    int b = blockIdx.z;
    int i0 = blockIdx.y * 64, j0 = blockIdx.x * 64;
    int tid = threadIdx.x;
    int ty = tid >> 4, tx = tid & 15;

    if (tid < AH / 4)
        ((float4*)sw2)[tid] = ((const float4*)w2)[tid];

    float acc[4][4];
#pragma unroll
    for (int r = 0; r < 4; r++)
#pragma unroll
        for (int c = 0; c < 4; c++) acc[r][c] = 0.f;

    const int row = tid >> 2;                        // 0..63
    const int prow = ((row & 3) << 4) | (row >> 2);  // permutation for spj

    for (int a0 = 0; a0 < AH; a0 += 32) {
        __syncthreads();
#pragma unroll
        for (int i = 0; i < 2; i++) {
            int f4 = (tid & 3) + 4 * i;
            float4 pv = *(const float4*)&g_pij[((long)(b * NN_NODES) + i0 + row) * AH + a0 + f4 * 4];
            float4 bv = *(const float4*)&b1[a0 + f4 * 4];
            pv.x += bv.x; pv.y += bv.y; pv.z += bv.z; pv.w += bv.w;
            *(float4*)&spi[row][f4 * 4] = pv;
            float4 qv = *(const float4*)&g_pij[PJOFF + ((long)(b * NN_NODES) + j0 + row) * AH + a0 + f4 * 4];
            *(float4*)&spj[prow][f4 * 4] = qv;
        }
        __syncthreads();
#pragma unroll
        for (int f4 = 0; f4 < 8; f4++) {
            float4 w4 = *(const float4*)&sw2[a0 + f4 * 4];
            float4 pi4[4], pj4[4];
#pragma unroll
            for (int r = 0; r < 4; r++) pi4[r] = *(const float4*)&spi[ty * 4 + r][f4 * 4];
#pragma unroll
            for (int c = 0; c < 4; c++) pj4[c] = *(const float4*)&spj[16 * c + tx][f4 * 4];
#pragma unroll
            for (int r = 0; r < 4; r++)
#pragma unroll
                for (int c = 0; c < 4; c++) {
                    acc[r][c] += fmaxf(pi4[r].x + pj4[c].x, 0.f) * w4.x
                               + fmaxf(pi4[r].y + pj4[c].y, 0.f) * w4.y
                               + fmaxf(pi4[r].z + pj4[c].z, 0.f) * w4.z
                               + fmaxf(pi4[r].w + pj4[c].w, 0.f) * w4.w;
                }
        }
    }

    float b2v = b2p[0];
    float mymax = -3.4e38f;
#pragma unroll
    for (int r = 0; r < 4; r++) {
        float4 o = make_float4((acc[r][0] + b2v) * 2.f, (acc[r][1] + b2v) * 2.f,
                               (acc[r][2] + b2v) * 2.f, (acc[r][3] + b2v) * 2.f);
        *(float4*)&g_sc[(long)b * NN2 + (long)(i0 + ty * 4 + r) * NN_NODES + j0 + tx * 4] = o;
        atomicAdd(&g_h16[b][enc_f(o.x) >> 16], 1u);
        atomicAdd(&g_h16[b][enc_f(o.y) >> 16], 1u);
        atomicAdd(&g_h16[b][enc_f(o.z) >> 16], 1u);
        atomicAdd(&g_h16[b][enc_f(o.w) >> 16], 1u);
        mymax = fmaxf(mymax, fmaxf(fmaxf(o.x, o.y), fmaxf(o.z, o.w)));
    }
    red[tid] = mymax;
    __syncthreads();
    for (int s = 128; s > 0; s >>= 1) {
        if (tid < s) red[tid] = fmaxf(red[tid], red[tid + s]);
        __syncthreads();
    }
    if (tid == 0) atomicMax(&g_mxu[b], enc_f(red[0]));
}

// ---------------- radix select: histB + pick ----------------
__global__ void histB_kernel()
{
    int b = blockIdx.y, blk = blockIdx.x, tid = threadIdx.x;
    unsigned hi = g_hi16[b];
    const float* sm = g_sc + (long)b * NN2;
    for (int i = blk * 256 + tid; i < NN2; i += 32 * 256) {
        unsigned e = enc_f(sm[i]);
        if ((e >> 16) == hi) atomicAdd(&g_h16[b][e & 0xFFFFu], 1u);
    }
}
__global__ void pick_kernel(int phase)
{
    __shared__ unsigned part[1024];
    __shared__ unsigned wsum[32];
    __shared__ int s_warp, s_thread;
    __shared__ unsigned s_base, s_base2;
    int b = blockIdx.x, tid = threadIdx.x, lane = tid & 31, wrp = tid >> 5;
    unsigned* bins = g_h16[b];
    unsigned rank = (phase == 0) ? (unsigned)THR_IDX : (unsigned)g_selrank[b];

    unsigned s = 0;
#pragma unroll 8
    for (int t = 0; t < 64; t++) s += bins[tid * 64 + t];
    part[tid] = s;
    unsigned wsv = s;
#pragma unroll
    for (int o = 16; o > 0; o >>= 1) wsv += __shfl_down_sync(0xffffffffu, wsv, o);
    if (lane == 0) wsum[wrp] = wsv;
    __syncthreads();

    if (tid == 0) {
        unsigned cum = 0; int w = 0;
        for (; w < 32; w++) { if (cum + wsum[w] > rank) break; cum += wsum[w]; }
        s_warp = w; s_base = cum;
    }
    __syncthreads();
    if (tid == s_warp * 32) {
        unsigned cum = s_base; int t = s_warp * 32;
        for (;; t++) { if (cum + part[t] > rank) break; cum += part[t]; }
        s_thread = t; s_base2 = cum;
    }
    __syncthreads();
    if (tid == s_thread) {
        unsigned cum = s_base2; int bin = tid * 64;
        for (;; bin++) { if (cum + bins[bin] > rank) break; cum += bins[bin]; }
        if (phase == 0) { g_hi16[b] = (unsigned)bin; g_selrank[b] = (int)(rank - cum); }
        else g_thrE[b] = (g_hi16[b] << 16) | (unsigned)bin;
    }
    __syncthreads();
    if (phase == 0) {
#pragma unroll 8
        for (int t = 0; t < 64; t++) bins[tid * 64 + t] = 0u;
    }
}

// ---------------- threshold + exp -> adj planes + partial sum ----------------
__global__ void thresh_kernel()
{
    int b = blockIdx.y, blk = blockIdx.x, tid = threadIdx.x;
    const float* sm = g_sc + (long)b * NN2;
    __nv_bfloat16* H = g_bf + O_ADJH + (long)b * NN2;
    __nv_bfloat16* L = g_bf + O_ADJL + (long)b * NN2;
    float mx = dec_f(g_mxu[b]);
    unsigned thr = g_thrE[b];
    float s = 0.f;
    for (int i = blk * 256 + tid; i < NN2; i += 64 * 256) {
        float v = sm[i];
        unsigned e = enc_f(v);
        float keep = (e >= thr) ? expf(v - mx) : 0.f;
        __nv_bfloat16 h, l;
        splitw(keep, h, l);
        H[i] = h; L[i] = l;
        s += keep;
    }
    __shared__ float sh[256];
    sh[tid] = s; __syncthreads();
    for (int q = 128; q > 0; q >>= 1) { if (tid < q) sh[tid] += sh[tid + q]; __syncthreads(); }
    if (tid == 0) g_part[b * 64 + blk] = sh[0];
}
__global__ void inv_kernel()
{
    __shared__ float sh[64];
    int b = blockIdx.x, tid = threadIdx.x;
    sh[tid] = g_part[b * 64 + tid];
    __syncthreads();
    for (int q = 32; q > 0; q >>= 1) { if (tid < q) sh[tid] += sh[tid + q]; __syncthreads(); }
    if (tid == 0) g_inv[b] = 1.0f / sh[0];
}

// ---------------- batchnorm + relu ----------------
template<bool WHL>
__global__ void bn_relu_kernel(float* __restrict__ h,
                               const float* __restrict__ ga,
                               const float* __restrict__ be, int C,
                               __nv_bfloat16* __restrict__ Hout,
                               __nv_bfloat16* __restrict__ Lout)
{
    __shared__ float sh[8][32], sh2[8][32];
    int c = blockIdx.x * 32 + threadIdx.x;
    int ry = threadIdx.y;
    float s = 0.f, s2 = 0.f;
    for (int r = ry; r < BN_M; r += 8) {
        float v = h[(long)r * C + c];
        s += v; s2 += v * v;
    }
    sh[ry][threadIdx.x] = s; sh2[ry][threadIdx.x] = s2;
    __syncthreads();
    if (ry == 0) {
        for (int r = 1; r < 8; r++) { s += sh[r][threadIdx.x]; s2 += sh2[r][threadIdx.x]; }
        float m = s / (float)BN_M;
        float v = s2 / (float)BN_M - m * m;
        sh[0][threadIdx.x] = m;
        sh2[0][threadIdx.x] = rsqrtf(v + 1e-5f);
    }
    __syncthreads();
    float m = sh[0][threadIdx.x], inv = sh2[0][threadIdx.x];
    float gg = ga[c], bb = be[c];
    for (int r = ry; r < BN_M; r += 8) {
        float v = h[(long)r * C + c];
        float y = fmaxf((v - m) * inv * gg + bb, 0.f);
        if (WHL) {
            __nv_bfloat16 hh, ll;
            splitw(y, hh, ll);
            Hout[(long)r * C + c] = hh;
            Lout[(long)r * C + c] = ll;
        } else {
            h[(long)r * C + c] = y;
        }
    }
}

// ---------------- mean pool + classifier ----------------
__global__ void head_kernel(const float* __restrict__ cls_w,
                            const float* __restrict__ cls_b,
                            float* __restrict__ out)
{
    __shared__ float acc4[4][OUTF];
    __shared__ float feat[OUTF];
    int b = blockIdx.x, tid = threadIdx.x; // 512 threads
    int r0 = tid >> 7, f = tid & 127;
    float s = 0.f;
    for (int r = r0; r < NN_NODES; r += 4)
        s += g_h2b[((long)b * NN_NODES + r) * OUTF + f];
    acc4[r0][f] = s;
    __syncthreads();
    if (tid < OUTF)
        feat[tid] = (acc4[0][tid] + acc4[1][tid] + acc4[2][tid] + acc4[3][tid]) / (float)NN_NODES;
    __syncthreads();
    if (tid < NCLS) {
        float acc = cls_b[tid];
        for (int ff = 0; ff < OUTF; ff++) acc += feat[ff] * cls_w[tid * OUTF + ff];
        out[b * NCLS + tid] = acc;
    }
}

// ---------------- launcher ----------------
extern "C" void kernel_launch(void* const* d_in, const int* in_sizes, int n_in,
                              void* d_out, int out_size)
{
    const float* x     = (const float*)d_in[0];
    const float* Wg    = (const float*)d_in[1];
    const float* attn  = (const float*)d_in[2];
    const float* W1    = (const float*)d_in[3];
    const float* b1    = (const float*)d_in[4];
    const float* w2    = (const float*)d_in[5];
    const float* b2    = (const float*)d_in[6];
    const float* gc1_w = (const float*)d_in[7];
    const float* gc1_b = (const float*)d_in[8];
    const float* bn1_g = (const float*)d_in[9];
    const float* bn1_b = (const float*)d_in[10];
    const float* bn2_g = (const float*)d_in[13];
    const float* bn2_b = (const float*)d_in[14];
    const float* gc2_w = (const float*)d_in[11];
    const float* gc2_b = (const float*)d_in[12];
    const float* cls_w = (const float*)d_in[15];
    const float* cls_b = (const float*)d_in[16];
    float* out = (float*)d_out;

    float *hp, *pij, *h1b, *h2b, *ginv;
    __nv_bfloat16* bf;
    cudaGetSymbolAddress((void**)&hp,  g_hp);
    cudaGetSymbolAddress((void**)&pij, g_pij);
    cudaGetSymbolAddress((void**)&h1b, g_h1b);
    cudaGetSymbolAddress((void**)&h2b, g_h2b);
    cudaGetSymbolAddress((void**)&ginv, g_inv);
    cudaGetSymbolAddress((void**)&bf, g_bf);

    __nv_bfloat16 *XH = bf + O_XH, *XL = bf + O_XL;
    __nv_bfloat16 *WGH = bf + O_WGH, *WGL = bf + O_WGL;
    __nv_bfloat16 *W1H = bf + O_W1H, *W1L = bf + O_W1L;
    __nv_bfloat16 *GC1H = bf + O_GC1H, *GC1L = bf + O_GC1L;
    __nv_bfloat16 *GC2H = bf + O_GC2H, *GC2L = bf + O_GC2L;
    __nv_bfloat16 *HPH = bf + O_HPH, *HPL = bf + O_HPL;
    __nv_bfloat16 *ALH = bf + O_ALH, *ALL_ = bf + O_ALL;
    __nv_bfloat16 *NFH = bf + O_NFH, *NFL = bf + O_NFL;
    __nv_bfloat16 *ADJH = bf + O_ADJH, *ADJL = bf + O_ADJL;
    __nv_bfloat16 *H1H = bf + O_H1H, *H1L = bf + O_H1L;
    __nv_bfloat16 *H1BH = bf + O_H1BH, *H1BL = bf + O_H1BL;
    __nv_bfloat16 *H2H = bf + O_H2H, *H2L = bf + O_H2L;

    // 0) fused init + all input conversions (one launch)
    initconv_kernel<<<(Q_TOT + 255) / 256, 256>>>(x, Wg, W1, gc1_w, gc2_w);

    // 1) hp = x @ Wg^T  -> fp32 + planes
    mma_gemm<true, false, false, true, true><<<dim3(16, 16, 1), 128>>>(
        XH, XL, FDIM, WGH, WGL, FDIM, 0, 0, 0, 0, nullptr, nullptr,
        hp, HPH, HPL, FDIM, 0, 0, FDIM, 1);

    // 2) s_i, s_j + sjmax
    sij_kernel<<<(BB * HEADS * NN_NODES * 32 + 255) / 256, 256>>>(attn);

    // 3a) softmax rows -> alpha planes
    alpha_kernel<<<dim3(NN_NODES / 8, BB * HEADS), 256>>>();

    // 3b) nf = alpha @ hp (per b,h) -> planes only
    mma_gemm<false, false, false, false, true><<<dim3(DH / 64, NN_NODES / 64, BB * HEADS), 128>>>(
        ALH, ALL_, NN_NODES, HPH, HPL, FDIM,
        (long)HEADS * NN2, (long)NN2, (long)NN_NODES * FDIM, (long)DH,
        nullptr, nullptr, nullptr, NFH, NFL, FDIM,
        (long)NN_NODES * FDIM, (long)DH, NN_NODES, HEADS);

    // 4) pi/pj fused -> fp32
    mma_gemm<true, false, false, true, false><<<dim3(AH / 64, 16, 2), 128>>>(
        NFH, NFL, FDIM, W1H, W1L, 2 * FDIM,
        0, 0, FDIM, 0, nullptr, nullptr,
        pij, nullptr, nullptr, AH, (long)PJOFF, 0, FDIM, 1);

    // 5) edge scores + global max + high-16 histogram (fused)
    edge_kernel<<<dim3(NN_NODES / 64, NN_NODES / 64, BB), 256>>>(b1, w2, b2);

    // 6) exact k-th order statistic
    pick_kernel<<<BB, 1024>>>(0);
    histB_kernel<<<dim3(32, BB), 256>>>();
    pick_kernel<<<BB, 1024>>>(1);

    // 7) threshold + exp -> adj planes; sum -> 1/denom
    thresh_kernel<<<dim3(64, BB), 256>>>();
    inv_kernel<<<BB, 64>>>();

    // 8) h1 = (adjU @ nf) * inv[b] -> planes
    mma_gemm<false, false, true, false, true><<<dim3(FDIM / 64, NN_NODES / 64, BB), 128>>>(
        ADJH, ADJL, NN_NODES, NFH, NFL, FDIM,
        (long)NN2, 0, (long)NN_NODES * FDIM, 0,
        nullptr, ginv, nullptr, H1H, H1L, FDIM,
        (long)NN_NODES * FDIM, 0, NN_NODES, 1);

    // 9) h1b = h1 @ gc1_w^T + gc1_b -> fp32
    mma_gemm<true, true, false, true, false><<<dim3(HID / 64, 16, 1), 128>>>(
        H1H, H1L, FDIM, GC1H, GC1L, FDIM,
        0, 0, 0, 0, gc1_b, nullptr,
        h1b, nullptr, nullptr, HID, 0, 0, FDIM, 1);

    // 10) bn1 + relu -> planes
    bn_relu_kernel<true><<<HID / 32, dim3(32, 8)>>>(h1b, bn1_g, bn1_b, HID, H1BH, H1BL);

    // 11) h2 = (adjU @ h1b) * inv[b] -> planes
    mma_gemm<false, false, true, false, true><<<dim3(HID / 64, NN_NODES / 64, BB), 128>>>(
        ADJH, ADJL, NN_NODES, H1BH, H1BL, HID,
        (long)NN2, 0, (long)NN_NODES * HID, 0,
        nullptr, ginv, nullptr, H2H, H2L, HID,
        (long)NN_NODES * HID, 0, NN_NODES, 1);

    // 12) h2b = h2 @ gc2_w^T + gc2_b -> fp32
    mma_gemm<true, true, false, true, false><<<dim3(OUTF / 64, 16, 1), 128>>>(
        H2H, H2L, HID, GC2H, GC2L, HID,
        0, 0, 0, 0, gc2_b, nullptr,
        h2b, nullptr, nullptr, OUTF, 0, 0, HID, 1);

    // 13) bn2 + relu (in place fp32)
    bn_relu_kernel<false><<<OUTF / 32, dim3(32, 8)>>>(h2b, bn2_g, bn2_b, OUTF, nullptr, nullptr);

    // 14) mean pool + classifier
    head_kernel<<<BB, 512>>>(cls_w, cls_b, out);
}

// round 15
// speedup vs baseline: 1.1384x; 1.0194x over previous
#include <cuda_runtime.h>
#include <cuda_bf16.h>
#include <math.h>

// ---------------- problem constants ----------------
#define BB 2
#define NN_NODES 512
#define FDIM 1024
#define HEADS 4
#define DH 256
#define AH 256
#define HID 512
#define OUTF 128
#define NCLS 10
#define NN2 (NN_NODES*NN_NODES)          // 262144
#define KSEL 209715                       // int(0.8 * N*N)
#define THR_IDX (NN2 - KSEL)              // 52429
#define BN_M (BB*NN_NODES)
#define PJOFF (BB*NN_NODES*AH)

// ---------------- fp32 scratch ----------------
__device__ float g_hp [BB*NN_NODES*FDIM];
__device__ float g_si [BB*HEADS*NN_NODES];
__device__ float g_sj [BB*HEADS*NN_NODES];
__device__ float g_pij[2*BB*NN_NODES*AH];
__device__ float g_sc [BB*NN2];
__device__ float g_h1b[BB*NN_NODES*HID];
__device__ float g_h2b[BB*NN_NODES*OUTF];
__device__ float g_part[BB*64];
__device__ float g_inv[BB];
__device__ unsigned g_mxu[BB];
__device__ unsigned g_sjmx[BB*HEADS];
__device__ unsigned g_h16[BB][65536];
__device__ unsigned g_hi16[BB];
__device__ int g_selrank[BB];
__device__ unsigned g_thrE[BB];

// ---------------- bf16 hi/lo plane arena ----------------
#define SZ_X    (BB*NN_NODES*FDIM)
#define SZ_WG   (FDIM*FDIM)
#define SZ_W1   (AH*2*FDIM)
#define SZ_GC1  (HID*FDIM)
#define SZ_GC2  (OUTF*HID)
#define SZ_HP   (BB*NN_NODES*FDIM)
#define SZ_AL   (BB*HEADS*NN2)
#define SZ_NF   (BB*NN_NODES*FDIM)
#define SZ_ADJ  (BB*NN2)
#define SZ_H1   (BB*NN_NODES*FDIM)
#define SZ_H1B  (BB*NN_NODES*HID)
#define SZ_H2   (BB*NN_NODES*HID)

#define O_XH   ((size_t)0)
#define O_XL   (O_XH   + SZ_X)
#define O_WGH  (O_XL   + SZ_X)
#define O_WGL  (O_WGH  + SZ_WG)
#define O_W1H  (O_WGL  + SZ_WG)
#define O_W1L  (O_W1H  + SZ_W1)
#define O_GC1H (O_W1L  + SZ_W1)
#define O_GC1L (O_GC1H + SZ_GC1)
#define O_GC2H (O_GC1L + SZ_GC1)
#define O_GC2L (O_GC2H + SZ_GC2)
#define O_HPH  (O_GC2L + SZ_GC2)
#define O_HPL  (O_HPH  + SZ_HP)
#define O_ALH  (O_HPL  + SZ_HP)
#define O_ALL  (O_ALH  + SZ_AL)
#define O_NFH  (O_ALL  + SZ_AL)
#define O_NFL  (O_NFH  + SZ_NF)
#define O_ADJH (O_NFL  + SZ_NF)
#define O_ADJL (O_ADJH + SZ_ADJ)
#define O_H1H  (O_ADJL + SZ_ADJ)
#define O_H1L  (O_H1H  + SZ_H1)
#define O_H1BH (O_H1L  + SZ_H1)
#define O_H1BL (O_H1BH + SZ_H1B)
#define O_H2H  (O_H1BL + SZ_H1B)
#define O_H2L  (O_H2H  + SZ_H2)
#define O_END  (O_H2L  + SZ_H2)

__device__ __nv_bfloat16 g_bf[O_END];

// ---------------- helpers ----------------
__device__ __forceinline__ unsigned enc_f(float f) {
    unsigned u = __float_as_uint(f);
    return (u & 0x80000000u) ? ~u : (u | 0x80000000u);
}
__device__ __forceinline__ float dec_f(unsigned e) {
    unsigned u = (e & 0x80000000u) ? (e ^ 0x80000000u) : ~e;
    return __uint_as_float(u);
}
__device__ __forceinline__ void splitw(float v, __nv_bfloat16& h, __nv_bfloat16& l) {
    h = __float2bfloat16_rn(v);
    l = __float2bfloat16_rn(v - __bfloat162float(h));
}
__device__ __forceinline__ unsigned smem_u32(const void* p) {
    unsigned a;
    asm("{ .reg .u64 t; cvta.to.shared.u64 t, %1; cvt.u32.u64 %0, t; }" : "=r"(a) : "l"(p));
    return a;
}

__device__ __forceinline__ void ldsm4(unsigned addr, unsigned& r0, unsigned& r1,
                                      unsigned& r2, unsigned& r3)
{
    asm volatile("ldmatrix.sync.aligned.m8n8.x4.shared.b16 {%0,%1,%2,%3}, [%4];"
                 : "=r"(r0), "=r"(r1), "=r"(r2), "=r"(r3) : "r"(addr));
}
__device__ __forceinline__ void ldsm4t(unsigned addr, unsigned& r0, unsigned& r1,
                                       unsigned& r2, unsigned& r3)
{
    asm volatile("ldmatrix.sync.aligned.m8n8.x4.trans.shared.b16 {%0,%1,%2,%3}, [%4];"
                 : "=r"(r0), "=r"(r1), "=r"(r2), "=r"(r3) : "r"(addr));
}

#define CP16(sa, gp) \
    asm volatile("cp.async.cg.shared.global [%0], [%1], 16;" :: "r"(sa), "l"(gp) : "memory")
#define CP_COMMIT() asm volatile("cp.async.commit_group;" ::: "memory")
#define CP_WAIT1()  asm volatile("cp.async.wait_group 1;" ::: "memory")

// ---------------- fused init + all f32->bf16 plane conversions ----------------
#define Q_X   (SZ_X/4)
#define Q_WG  (SZ_WG/4)
#define Q_W1  (SZ_W1/4)
#define Q_GC1 (SZ_GC1/4)
#define Q_GC2 (SZ_GC2/4)
#define Q_TOT (Q_X+Q_WG+Q_W1+Q_GC1+Q_GC2)
__global__ void initconv_kernel(const float* __restrict__ x,
                                const float* __restrict__ wg,
                                const float* __restrict__ w1,
                                const float* __restrict__ gc1,
                                const float* __restrict__ gc2)
{
    int q = blockIdx.x * 256 + threadIdx.x;
    if (q < BB * 65536) {
        ((unsigned*)g_h16)[q] = 0u;
        if (q < BB) g_mxu[q] = 0u;
        if (q < BB * HEADS) g_sjmx[q] = 0u;
    }
    if (q >= Q_TOT) return;
    const float* src; __nv_bfloat16 *H, *L; int lq = q;
    if (lq < Q_X)        { src = x;   H = g_bf + O_XH;   L = g_bf + O_XL; }
    else if ((lq -= Q_X)   < Q_WG)  { src = wg;  H = g_bf + O_WGH;  L = g_bf + O_WGL; }
    else if ((lq -= Q_WG)  < Q_W1)  { src = w1;  H = g_bf + O_W1H;  L = g_bf + O_W1L; }
    else if ((lq -= Q_W1)  < Q_GC1) { src = gc1; H = g_bf + O_GC1H; L = g_bf + O_GC1L; }
    else { lq -= Q_GC1;               src = gc2; H = g_bf + O_GC2H; L = g_bf + O_GC2L; }
    float4 v = ((const float4*)src)[lq];
    __nv_bfloat162 h0 = __floats2bfloat162_rn(v.x, v.y);
    __nv_bfloat162 h1 = __floats2bfloat162_rn(v.z, v.w);
    float2 f0 = __bfloat1622float2(h0);
    float2 f1 = __bfloat1622float2(h1);
    __nv_bfloat162 l0 = __floats2bfloat162_rn(v.x - f0.x, v.y - f0.y);
    __nv_bfloat162 l1 = __floats2bfloat162_rn(v.z - f1.x, v.w - f1.y);
    *reinterpret_cast<__nv_bfloat162*>(H + 4*lq)     = h0;
    *reinterpret_cast<__nv_bfloat162*>(H + 4*lq + 2) = h1;
    *reinterpret_cast<__nv_bfloat162*>(L + 4*lq)     = l0;
    *reinterpret_cast<__nv_bfloat162*>(L + 4*lq + 2) = l1;
}

// ---------------- bf16 split-operand GEMM, 3-stage cp.async pipeline ----------------
// BM=64, BN=64, 128 threads, warp tile 32x32, K-tile 32.
#define AP  40
#define BPN 72
#define PSZ 2560                       // elems per plane-buffer
#define STGB (4*PSZ*2)                 // bytes per stage (4 planes) = 20480
#define GSMEM (3*STGB)                 // 61440
template<bool TRANSB, bool BIAS, bool SCALE, bool WF32, bool WHL>
__global__ void __launch_bounds__(128) mma_gemm(
    const __nv_bfloat16* __restrict__ AH_, const __nv_bfloat16* __restrict__ AL_, int lda,
    const __nv_bfloat16* __restrict__ BH_, const __nv_bfloat16* __restrict__ BL_, int ldb,
    long sA, long sA2, long sB, long sB2,
    const float* __restrict__ bias, const float* __restrict__ scale,
    float* __restrict__ C, __nv_bfloat16* __restrict__ CH, __nv_bfloat16* __restrict__ CL,
    int ldc, long sC, long sC2, int K, int zdiv)
{
    extern __shared__ __align__(16) __nv_bfloat16 smp[];
    const unsigned base = smem_u32(smp);

    const int bz = blockIdx.z;
    const int z1 = bz / zdiv, z2 = bz % zdiv;
    const __nv_bfloat16* Ah_g = AH_ + z1 * sA + z2 * sA2;
    const __nv_bfloat16* Al_g = AL_ + z1 * sA + z2 * sA2;
    const __nv_bfloat16* Bh_g = BH_ + z1 * sB + z2 * sB2;
    const __nv_bfloat16* Bl_g = BL_ + z1 * sB + z2 * sB2;
    const long offC_g = z1 * sC + z2 * sC2;

    const int m0 = blockIdx.y * 64;
    const int n0 = blockIdx.x * 64;
    const int tid = threadIdx.x;
    const int lane = tid & 31;
    const int wid  = tid >> 5;
    const int wm = wid >> 1, wn = wid & 1;
    const int g  = lane >> 2;
    const int tg = lane & 3;

    // staging indices
    const int a_r = tid >> 2;           // 0..31 (+32)
    const int a_c8 = (tid & 3) * 8;
    const int b_kr = tid >> 3;          // 0..15 (+16)
    const int b_nc = (tid & 7) * 8;

    // ldmatrix per-lane offsets (elements within a plane)
    const int l7 = lane & 7;
    const int lb3 = (lane >> 3) & 1;
    const int lb4 = lane >> 4;
    const int offA  = (wm * 32 + l7 + 8 * lb3) * AP + 8 * lb4;
    const int offBT = (wn * 32 + l7 + 8 * lb4) * AP + 8 * lb3;
    const int offBN = (l7 + 8 * lb3) * BPN + wn * 32 + 8 * lb4;

    float acc[2][4][4];
#pragma unroll
    for (int im = 0; im < 2; im++)
#pragma unroll
        for (int in = 0; in < 4; in++)
#pragma unroll
            for (int q = 0; q < 4; q++) acc[im][in][q] = 0.f;

    const int niter = K >> 5;

#define MMAB(d, a, b0, b1)                                                    \
    asm volatile("mma.sync.aligned.m16n8k16.row.col.f32.bf16.bf16.f32 "       \
                 "{%0,%1,%2,%3}, {%4,%5,%6,%7}, {%8,%9}, {%0,%1,%2,%3};"      \
                 : "+f"(d[0]), "+f"(d[1]), "+f"(d[2]), "+f"(d[3])             \
                 : "r"(a[0]), "r"(a[1]), "r"(a[2]), "r"(a[3]), "r"(b0), "r"(b1))

    // issue loads for K-chunk ks into stage ks%3 (always commits, maybe empty)
    auto issue = [&](int ks) {
        if (ks < niter) {
            const unsigned sb = base + (unsigned)(ks % 3) * STGB;
            const int k0 = ks << 5;
#pragma unroll
            for (int i = 0; i < 2; i++) {
                int m = a_r + 32 * i;
                CP16(sb + 2u * (m * AP + a_c8),
                     &Ah_g[(long)(m0 + m) * lda + k0 + a_c8]);
                CP16(sb + 2u * (PSZ + m * AP + a_c8),
                     &Al_g[(long)(m0 + m) * lda + k0 + a_c8]);
                if (TRANSB) {
                    CP16(sb + 2u * (2 * PSZ + m * AP + a_c8),
                         &Bh_g[(long)(n0 + m) * ldb + k0 + a_c8]);
                    CP16(sb + 2u * (3 * PSZ + m * AP + a_c8),
                         &Bl_g[(long)(n0 + m) * ldb + k0 + a_c8]);
                } else {
                    int kk = b_kr + 16 * i;
                    CP16(sb + 2u * (2 * PSZ + kk * BPN + b_nc),
                         &Bh_g[(long)(k0 + kk) * ldb + n0 + b_nc]);
                    CP16(sb + 2u * (3 * PSZ + kk * BPN + b_nc),
                         &Bl_g[(long)(k0 + kk) * ldb + n0 + b_nc]);
                }
            }
        }
        CP_COMMIT();
    };

    issue(0);
    issue(1);

    for (int it = 0; it < niter; it++) {
        CP_WAIT1();          // own copies for stage `it` complete
        __syncthreads();     // everyone's copies for stage `it` visible;
                             // also: all warps done computing stage (it-1)%3
        issue(it + 2);       // writes stage (it+2)%3 == (it-1)%3 — safe after sync

        const unsigned sb = base + (unsigned)(it % 3) * STGB;
        const unsigned aH = sb;
        const unsigned aL = sb + 2u * PSZ;
        const unsigned bH = sb + 4u * PSZ;
        const unsigned bL = sb + 6u * PSZ;
#pragma unroll
        for (int ks = 0; ks < 2; ks++) {
            unsigned ah[2][4], al4[2][4], bh[2][4], bl[2][4];
#pragma unroll
            for (int im = 0; im < 2; im++) {
                unsigned off = 2u * (offA + im * 16 * AP + ks * 16);
                ldsm4(aH + off, ah[im][0], ah[im][1], ah[im][2], ah[im][3]);
                ldsm4(aL + off, al4[im][0], al4[im][1], al4[im][2], al4[im][3]);
            }
#pragma unroll
            for (int q = 0; q < 2; q++) {
                if (TRANSB) {
                    unsigned off = 2u * (offBT + q * 16 * AP + ks * 16);
                    ldsm4(bH + off, bh[q][0], bh[q][1], bh[q][2], bh[q][3]);
                    ldsm4(bL + off, bl[q][0], bl[q][1], bl[q][2], bl[q][3]);
                } else {
                    unsigned off = 2u * (offBN + q * 16 + ks * 16 * BPN);
                    ldsm4t(bH + off, bh[q][0], bh[q][1], bh[q][2], bh[q][3]);
                    ldsm4t(bL + off, bl[q][0], bl[q][1], bl[q][2], bl[q][3]);
                }
            }
#pragma unroll
            for (int im = 0; im < 2; im++)
#pragma unroll
                for (int in = 0; in < 4; in++) {
                    int q = in >> 1, p = (in & 1) * 2;
                    MMAB(acc[im][in], al4[im], bh[q][p], bh[q][p + 1]);
                    MMAB(acc[im][in], ah[im],  bl[q][p], bl[q][p + 1]);
                    MMAB(acc[im][in], ah[im],  bh[q][p], bh[q][p + 1]);
                }
        }
    }

    float scv = SCALE ? scale[z1] : 1.f;
    float* Cp = C + offC_g;
    __nv_bfloat16* CHp = CH + offC_g;
    __nv_bfloat16* CLp = CL + offC_g;
#pragma unroll
    for (int im = 0; im < 2; im++) {
        int r0 = m0 + wm * 32 + im * 16 + g;
        int r1 = r0 + 8;
#pragma unroll
        for (int in = 0; in < 4; in++) {
            int c = n0 + wn * 32 + in * 8 + 2 * tg;
            float b0 = 0.f, b1v = 0.f;
            if (BIAS) { b0 = bias[c]; b1v = bias[c + 1]; }
            float2 v0, v1;
            if (SCALE) {
                v0 = make_float2(acc[im][in][0] * scv, acc[im][in][1] * scv);
                v1 = make_float2(acc[im][in][2] * scv, acc[im][in][3] * scv);
            } else {
                v0 = make_float2(acc[im][in][0] + b0, acc[im][in][1] + b1v);
                v1 = make_float2(acc[im][in][2] + b0, acc[im][in][3] + b1v);
            }
            if (WF32) {
                *(float2*)&Cp[(long)r0 * ldc + c] = v0;
                *(float2*)&Cp[(long)r1 * ldc + c] = v1;
            }
            if (WHL) {
                __nv_bfloat162 h0 = __floats2bfloat162_rn(v0.x, v0.y);
                __nv_bfloat162 h1 = __floats2bfloat162_rn(v1.x, v1.y);
                float2 f0 = __bfloat1622float2(h0);
                float2 f1 = __bfloat1622float2(h1);
                __nv_bfloat162 l0 = __floats2bfloat162_rn(v0.x - f0.x, v0.y - f0.y);
                __nv_bfloat162 l1 = __floats2bfloat162_rn(v1.x - f1.x, v1.y - f1.y);
                *reinterpret_cast<__nv_bfloat162*>(&CHp[(long)r0 * ldc + c]) = h0;
                *reinterpret_cast<__nv_bfloat162*>(&CHp[(long)r1 * ldc + c]) = h1;
                *reinterpret_cast<__nv_bfloat162*>(&CLp[(long)r0 * ldc + c]) = l0;
                *reinterpret_cast<__nv_bfloat162*>(&CLp[(long)r1 * ldc + c]) = l1;
            }
        }
    }
#undef MMAB
}

// ---------------- s_i, s_j + per-(b,h) max of s_j ----------------
__global__ void sij_kernel(const float* __restrict__ attn)
{
    int gw = (blockIdx.x * blockDim.x + threadIdx.x) >> 5;
    int lane = threadIdx.x & 31;
    if (gw >= BB * HEADS * NN_NODES) return;
    int b = gw / (HEADS * NN_NODES);
    int r = gw % (HEADS * NN_NODES);
    int h = r / NN_NODES;
    int n = r % NN_NODES;
    const float* hp = g_hp + ((long)(b * NN_NODES + n)) * FDIM + h * DH;
    const float* ai = attn + h * 2 * DH;
    float si = 0.f, sj = 0.f;
#pragma unroll
    for (int d = lane; d < DH; d += 32) {
        float v = hp[d];
        si += v * ai[d];
        sj += v * ai[DH + d];
    }
#pragma unroll
    for (int o = 16; o > 0; o >>= 1) {
        si += __shfl_down_sync(0xffffffffu, si, o);
        sj += __shfl_down_sync(0xffffffffu, sj, o);
    }
    if (lane == 0) {
        g_si[gw] = si;
        g_sj[gw] = sj;
        atomicMax(&g_sjmx[b * HEADS + h], enc_f(sj));
    }
}

// ---------------- attention softmax rows -> alpha planes ----------------
__global__ void alpha_kernel()
{
    __shared__ float sj[NN_NODES];
    int bh = blockIdx.y;
    int tid = threadIdx.x;
    for (int j = tid; j < NN_NODES; j += 256) sj[j] = g_sj[bh * NN_NODES + j];
    __syncthreads();

    int wrp = tid >> 5, lane = tid & 31;
    int i = blockIdx.x * 8 + wrp;
    float si = g_si[bh * NN_NODES + i];
    float sjmax = dec_f(g_sjmx[bh]);
    float M = si + sjmax;
    M = (M >= 0.f) ? M : 0.2f * M;
    float p[16];
    float sum = 0.f;
#pragma unroll
    for (int t = 0; t < 16; t++) {
        float e = si + sj[lane + 32 * t];
        e = (e >= 0.f) ? e : 0.2f * e;
        p[t] = expf(e - M);
        sum += p[t];
    }
#pragma unroll
    for (int o = 16; o > 0; o >>= 1) sum += __shfl_xor_sync(0xffffffffu, sum, o);
    float inv = 1.0f / sum;
    long base = (long)bh * NN2 + (long)i * NN_NODES;
    __nv_bfloat16* H = g_bf + O_ALH + base;
    __nv_bfloat16* L = g_bf + O_ALL + base;
#pragma unroll
    for (int t = 0; t < 16; t++) {
        float v = p[t] * inv;
        __nv_bfloat16 h, l;
        splitw(v, h, l);
        H[lane + 32 * t] = h;
        L[lane + 32 * t] = l;
    }
}

// ---------------- edge MLP: 64x64 edges/block, 4x4 per thread ----------------
__global__ void __launch_bounds__(256) edge_kernel(
    const float* __restrict__ b1,
    const float* __restrict__ w2,
    const float* __restrict__ b2p)
{
    __shared__ float spi[64][36];
    __shared__ float spj[64][36];
    __shared__ float sw2[AH];
    __shared__ float red[256];
    int b = blockIdx.z;
    int i0 = blockIdx.y * 64, j0 = blockIdx.x * 64;
    int tid = threadIdx.x;
    int ty = tid >> 4, tx = tid & 15;

    if (tid < AH / 4)
        ((float4*)sw2)[tid] = ((const float4*)w2)[tid];

    float acc[4][4];
#pragma unroll
    for (int r = 0; r < 4; r++)
#pragma unroll
        for (int c = 0; c < 4; c++) acc[r][c] = 0.f;

    const int row = tid >> 2;
    const int prow = ((row & 3) << 4) | (row >> 2);

    for (int a0 = 0; a0 < AH; a0 += 32) {
        __syncthreads();
#pragma unroll
        for (int i = 0; i < 2; i++) {
            int f4 = (tid & 3) + 4 * i;
            float4 pv = *(const float4*)&g_pij[((long)(b * NN_NODES) + i0 + row) * AH + a0 + f4 * 4];
            float4 bv = *(const float4*)&b1[a0 + f4 * 4];
            pv.x += bv.x; pv.y += bv.y; pv.z += bv.z; pv.w += bv.w;
            *(float4*)&spi[row][f4 * 4] = pv;
            float4 qv = *(const float4*)&g_pij[PJOFF + ((long)(b * NN_NODES) + j0 + row) * AH + a0 + f4 * 4];
            *(float4*)&spj[prow][f4 * 4] = qv;
        }
        __syncthreads();
#pragma unroll
        for (int f4 = 0; f4 < 8; f4++) {
            float4 w4 = *(const float4*)&sw2[a0 + f4 * 4];
            float4 pi4[4], pj4[4];
#pragma unroll
            for (int r = 0; r < 4; r++) pi4[r] = *(const float4*)&spi[ty * 4 + r][f4 * 4];
#pragma unroll
            for (int c = 0; c < 4; c++) pj4[c] = *(const float4*)&spj[16 * c + tx][f4 * 4];
#pragma unroll
            for (int r = 0; r < 4; r++)
#pragma unroll
                for (int c = 0; c < 4; c++) {
                    acc[r][c] += fmaxf(pi4[r].x + pj4[c].x, 0.f) * w4.x
                               + fmaxf(pi4[r].y + pj4[c].y, 0.f) * w4.y
                               + fmaxf(pi4[r].z + pj4[c].z, 0.f) * w4.z
                               + fmaxf(pi4[r].w + pj4[c].w, 0.f) * w4.w;
                }
        }
    }

    float b2v = b2p[0];
    float mymax = -3.4e38f;
#pragma unroll
    for (int r = 0; r < 4; r++) {
        float4 o = make_float4((acc[r][0] + b2v) * 2.f, (acc[r][1] + b2v) * 2.f,
                               (acc[r][2] + b2v) * 2.f, (acc[r][3] + b2v) * 2.f);
        *(float4*)&g_sc[(long)b * NN2 + (long)(i0 + ty * 4 + r) * NN_NODES + j0 + tx * 4] = o;
        atomicAdd(&g_h16[b][enc_f(o.x) >> 16], 1u);
        atomicAdd(&g_h16[b][enc_f(o.y) >> 16], 1u);
        atomicAdd(&g_h16[b][enc_f(o.z) >> 16], 1u);
        atomicAdd(&g_h16[b][enc_f(o.w) >> 16], 1u);
        mymax = fmaxf(mymax, fmaxf(fmaxf(o.x, o.y), fmaxf(o.z, o.w)));
    }
    red[tid] = mymax;
    __syncthreads();
    for (int s = 128; s > 0; s >>= 1) {
        if (tid < s) red[tid] = fmaxf(red[tid], red[tid + s]);
        __syncthreads();
    }
    if (tid == 0) atomicMax(&g_mxu[b], enc_f(red[0]));
}

// ---------------- radix select: histB + pick ----------------
__global__ void histB_kernel()
{
    int b = blockIdx.y, blk = blockIdx.x, tid = threadIdx.x;
    unsigned hi = g_hi16[b];
    const float* sm = g_sc + (long)b * NN2;
    for (int i = blk * 256 + tid; i < NN2; i += 32 * 256) {
        unsigned e = enc_f(sm[i]);
        if ((e >> 16) == hi) atomicAdd(&g_h16[b][e & 0xFFFFu], 1u);
    }
}
__global__ void pick_kernel(int phase)
{
    __shared__ unsigned part[1024];
    __shared__ unsigned wsum[32];
    __shared__ int s_warp, s_thread;
    __shared__ unsigned s_base, s_base2;
    int b = blockIdx.x, tid = threadIdx.x, lane = tid & 31, wrp = tid >> 5;
    unsigned* bins = g_h16[b];
    unsigned rank = (phase == 0) ? (unsigned)THR_IDX : (unsigned)g_selrank[b];

    unsigned s = 0;
#pragma unroll 8
    for (int t = 0; t < 64; t++) s += bins[tid * 64 + t];
    part[tid] = s;
    unsigned wsv = s;
#pragma unroll
    for (int o = 16; o > 0; o >>= 1) wsv += __shfl_down_sync(0xffffffffu, wsv, o);
    if (lane == 0) wsum[wrp] = wsv;
    __syncthreads();

    if (tid == 0) {
        unsigned cum = 0; int w = 0;
        for (; w < 32; w++) { if (cum + wsum[w] > rank) break; cum += wsum[w]; }
        s_warp = w; s_base = cum;
    }
    __syncthreads();
    if (tid == s_warp * 32) {
        unsigned cum = s_base; int t = s_warp * 32;
        for (;; t++) { if (cum + part[t] > rank) break; cum += part[t]; }
        s_thread = t; s_base2 = cum;
    }
    __syncthreads();
    if (tid == s_thread) {
        unsigned cum = s_base2; int bin = tid * 64;
        for (;; bin++) { if (cum + bins[bin] > rank) break; cum += bins[bin]; }
        if (phase == 0) { g_hi16[b] = (unsigned)bin; g_selrank[b] = (int)(rank - cum); }
        else g_thrE[b] = (g_hi16[b] << 16) | (unsigned)bin;
    }
    __syncthreads();
    if (phase == 0) {
#pragma unroll 8
        for (int t = 0; t < 64; t++) bins[tid * 64 + t] = 0u;
    }
}

// ---------------- threshold + exp -> adj planes + partial sum ----------------
__global__ void thresh_kernel()
{
    int b = blockIdx.y, blk = blockIdx.x, tid = threadIdx.x;
    const float* sm = g_sc + (long)b * NN2;
    __nv_bfloat16* H = g_bf + O_ADJH + (long)b * NN2;
    __nv_bfloat16* L = g_bf + O_ADJL + (long)b * NN2;
    float mx = dec_f(g_mxu[b]);
    unsigned thr = g_thrE[b];
    float s = 0.f;
    for (int i = blk * 256 + tid; i < NN2; i += 64 * 256) {
        float v = sm[i];
        unsigned e = enc_f(v);
        float keep = (e >= thr) ? expf(v - mx) : 0.f;
        __nv_bfloat16 h, l;
        splitw(keep, h, l);
        H[i] = h; L[i] = l;
        s += keep;
    }
    __shared__ float sh[256];
    sh[tid] = s; __syncthreads();
    for (int q = 128; q > 0; q >>= 1) { if (tid < q) sh[tid] += sh[tid + q]; __syncthreads(); }
    if (tid == 0) g_part[b * 64 + blk] = sh[0];
}
__global__ void inv_kernel()
{
    __shared__ float sh[64];
    int b = blockIdx.x, tid = threadIdx.x;
    sh[tid] = g_part[b * 64 + tid];
    __syncthreads();
    for (int q = 32; q > 0; q >>= 1) { if (tid < q) sh[tid] += sh[tid + q]; __syncthreads(); }
    if (tid == 0) g_inv[b] = 1.0f / sh[0];
}

// ---------------- batchnorm + relu ----------------
template<bool WHL>
__global__ void bn_relu_kernel(float* __restrict__ h,
                               const float* __restrict__ ga,
                               const float* __restrict__ be, int C,
                               __nv_bfloat16* __restrict__ Hout,
                               __nv_bfloat16* __restrict__ Lout)
{
    __shared__ float sh[8][32], sh2[8][32];
    int c = blockIdx.x * 32 + threadIdx.x;
    int ry = threadIdx.y;
    float s = 0.f, s2 = 0.f;
    for (int r = ry; r < BN_M; r += 8) {
        float v = h[(long)r * C + c];
        s += v; s2 += v * v;
    }
    sh[ry][threadIdx.x] = s; sh2[ry][threadIdx.x] = s2;
    __syncthreads();
    if (ry == 0) {
        for (int r = 1; r < 8; r++) { s += sh[r][threadIdx.x]; s2 += sh2[r][threadIdx.x]; }
        float m = s / (float)BN_M;
        float v = s2 / (float)BN_M - m * m;
        sh[0][threadIdx.x] = m;
        sh2[0][threadIdx.x] = rsqrtf(v + 1e-5f);
    }
    __syncthreads();
    float m = sh[0][threadIdx.x], inv = sh2[0][threadIdx.x];
    float gg = ga[c], bb = be[c];
    for (int r = ry; r < BN_M; r += 8) {
        float v = h[(long)r * C + c];
        float y = fmaxf((v - m) * inv * gg + bb, 0.f);
        if (WHL) {
            __nv_bfloat16 hh, ll;
            splitw(y, hh, ll);
            Hout[(long)r * C + c] = hh;
            Lout[(long)r * C + c] = ll;
        } else {
            h[(long)r * C + c] = y;
        }
    }
}

// ---------------- mean pool + classifier ----------------
__global__ void head_kernel(const float* __restrict__ cls_w,
                            const float* __restrict__ cls_b,
                            float* __restrict__ out)
{
    __shared__ float acc4[4][OUTF];
    __shared__ float feat[OUTF];
    int b = blockIdx.x, tid = threadIdx.x;
    int r0 = tid >> 7, f = tid & 127;
    float s = 0.f;
    for (int r = r0; r < NN_NODES; r += 4)
        s += g_h2b[((long)b * NN_NODES + r) * OUTF + f];
    acc4[r0][f] = s;
    __syncthreads();
    if (tid < OUTF)
        feat[tid] = (acc4[0][tid] + acc4[1][tid] + acc4[2][tid] + acc4[3][tid]) / (float)NN_NODES;
    __syncthreads();
    if (tid < NCLS) {
        float acc = cls_b[tid];
        for (int ff = 0; ff < OUTF; ff++) acc += feat[ff] * cls_w[tid * OUTF + ff];
        out[b * NCLS + tid] = acc;
    }
}

// ---------------- launcher ----------------
extern "C" void kernel_launch(void* const* d_in, const int* in_sizes, int n_in,
                              void* d_out, int out_size)
{
    const float* x     = (const float*)d_in[0];
    const float* Wg    = (const float*)d_in[1];
    const float* attn  = (const float*)d_in[2];
    const float* W1    = (const float*)d_in[3];
    const float* b1    = (const float*)d_in[4];
    const float* w2    = (const float*)d_in[5];
    const float* b2    = (const float*)d_in[6];
    const float* gc1_w = (const float*)d_in[7];
    const float* gc1_b = (const float*)d_in[8];
    const float* bn1_g = (const float*)d_in[9];
    const float* bn1_b = (const float*)d_in[10];
    const float* gc2_w = (const float*)d_in[11];
    const float* gc2_b = (const float*)d_in[12];
    const float* bn2_g = (const float*)d_in[13];
    const float* bn2_b = (const float*)d_in[14];
    const float* cls_w = (const float*)d_in[15];
    const float* cls_b = (const float*)d_in[16];
    float* out = (float*)d_out;

    float *hp, *pij, *h1b, *h2b, *ginv;
    __nv_bfloat16* bf;
    cudaGetSymbolAddress((void**)&hp,  g_hp);
    cudaGetSymbolAddress((void**)&pij, g_pij);
    cudaGetSymbolAddress((void**)&h1b, g_h1b);
    cudaGetSymbolAddress((void**)&h2b, g_h2b);
    cudaGetSymbolAddress((void**)&ginv, g_inv);
    cudaGetSymbolAddress((void**)&bf, g_bf);

    __nv_bfloat16 *XH = bf + O_XH, *XL = bf + O_XL;
    __nv_bfloat16 *WGH = bf + O_WGH, *WGL = bf + O_WGL;
    __nv_bfloat16 *W1H = bf + O_W1H, *W1L = bf + O_W1L;
    __nv_bfloat16 *GC1H = bf + O_GC1H, *GC1L = bf + O_GC1L;
    __nv_bfloat16 *GC2H = bf + O_GC2H, *GC2L = bf + O_GC2L;
    __nv_bfloat16 *HPH = bf + O_HPH, *HPL = bf + O_HPL;
    __nv_bfloat16 *ALH = bf + O_ALH, *ALL_ = bf + O_ALL;
    __nv_bfloat16 *NFH = bf + O_NFH, *NFL = bf + O_NFL;
    __nv_bfloat16 *ADJH = bf + O_ADJH, *ADJL = bf + O_ADJL;
    __nv_bfloat16 *H1H = bf + O_H1H, *H1L = bf + O_H1L;
    __nv_bfloat16 *H1BH = bf + O_H1BH, *H1BL = bf + O_H1BL;
    __nv_bfloat16 *H2H = bf + O_H2H, *H2L = bf + O_H2L;

    cudaFuncSetAttribute(mma_gemm<true,  false, false, true,  true >, cudaFuncAttributeMaxDynamicSharedMemorySize, GSMEM);
    cudaFuncSetAttribute(mma_gemm<false, false, false, false, true >, cudaFuncAttributeMaxDynamicSharedMemorySize, GSMEM);
    cudaFuncSetAttribute(mma_gemm<true,  false, false, true,  false>, cudaFuncAttributeMaxDynamicSharedMemorySize, GSMEM);
    cudaFuncSetAttribute(mma_gemm<false, false, true,  false, true >, cudaFuncAttributeMaxDynamicSharedMemorySize, GSMEM);
    cudaFuncSetAttribute(mma_gemm<true,  true,  false, true,  false>, cudaFuncAttributeMaxDynamicSharedMemorySize, GSMEM);

    // 0) fused init + all input conversions
    initconv_kernel<<<(Q_TOT + 255) / 256, 256>>>(x, Wg, W1, gc1_w, gc2_w);

    // 1) hp = x @ Wg^T  -> fp32 + planes
    mma_gemm<true, false, false, true, true><<<dim3(16, 16, 1), 128, GSMEM>>>(
        XH, XL, FDIM, WGH, WGL, FDIM, 0, 0, 0, 0, nullptr, nullptr,
        hp, HPH, HPL, FDIM, 0, 0, FDIM, 1);

    // 2) s_i, s_j + sjmax
    sij_kernel<<<(BB * HEADS * NN_NODES * 32 + 255) / 256, 256>>>(attn);

    // 3a) softmax rows -> alpha planes
    alpha_kernel<<<dim3(NN_NODES / 8, BB * HEADS), 256>>>();

    // 3b) nf = alpha @ hp (per b,h) -> planes only
    mma_gemm<false, false, false, false, true><<<dim3(DH / 64, NN_NODES / 64, BB * HEADS), 128, GSMEM>>>(
        ALH, ALL_, NN_NODES, HPH, HPL, FDIM,
        (long)HEADS * NN2, (long)NN2, (long)NN_NODES * FDIM, (long)DH,
        nullptr, nullptr, nullptr, NFH, NFL, FDIM,
        (long)NN_NODES * FDIM, (long)DH, NN_NODES, HEADS);

    // 4) pi/pj fused -> fp32
    mma_gemm<true, false, false, true, false><<<dim3(AH / 64, 16, 2), 128, GSMEM>>>(
        NFH, NFL, FDIM, W1H, W1L, 2 * FDIM,
        0, 0, FDIM, 0, nullptr, nullptr,
        pij, nullptr, nullptr, AH, (long)PJOFF, 0, FDIM, 1);

    // 5) edge scores + global max + high-16 histogram (fused)
    edge_kernel<<<dim3(NN_NODES / 64, NN_NODES / 64, BB), 256>>>(b1, w2, b2);

    // 6) exact k-th order statistic
    pick_kernel<<<BB, 1024>>>(0);
    histB_kernel<<<dim3(32, BB), 256>>>();
    pick_kernel<<<BB, 1024>>>(1);

    // 7) threshold + exp -> adj planes; sum -> 1/denom
    thresh_kernel<<<dim3(64, BB), 256>>>();
    inv_kernel<<<BB, 64>>>();

    // 8) h1 = (adjU @ nf) * inv[b] -> planes
    mma_gemm<false, false, true, false, true><<<dim3(FDIM / 64, NN_NODES / 64, BB), 128, GSMEM>>>(
        ADJH, ADJL, NN_NODES, NFH, NFL, FDIM,
        (long)NN2, 0, (long)NN_NODES * FDIM, 0,
        nullptr, ginv, nullptr, H1H, H1L, FDIM,
        (long)NN_NODES * FDIM, 0, NN_NODES, 1);

    // 9) h1b = h1 @ gc1_w^T + gc1_b -> fp32
    mma_gemm<true, true, false, true, false><<<dim3(HID / 64, 16, 1), 128, GSMEM>>>(
        H1H, H1L, FDIM, GC1H, GC1L, FDIM,
        0, 0, 0, 0, gc1_b, nullptr,
        h1b, nullptr, nullptr, HID, 0, 0, FDIM, 1);

    // 10) bn1 + relu -> planes
    bn_relu_kernel<true><<<HID / 32, dim3(32, 8)>>>(h1b, bn1_g, bn1_b, HID, H1BH, H1BL);

    // 11) h2 = (adjU @ h1b) * inv[b] -> planes
    mma_gemm<false, false, true, false, true><<<dim3(HID / 64, NN_NODES / 64, BB), 128, GSMEM>>>(
        ADJH, ADJL, NN_NODES, H1BH, H1BL, HID,
        (long)NN2, 0, (long)NN_NODES * HID, 0,
        nullptr, ginv, nullptr, H2H, H2L, HID,
        (long)NN_NODES * HID, 0, NN_NODES, 1);

    // 12) h2b = h2 @ gc2_w^T + gc2_b -> fp32
    mma_gemm<true, true, false, true, false><<<dim3(OUTF / 64, 16, 1), 128, GSMEM>>>(
        H2H, H2L, HID, GC2H, GC2L, HID,
        0, 0, 0, 0, gc2_b, nullptr,
        h2b, nullptr, nullptr, OUTF, 0, 0, HID, 1);

    // 13) bn2 + relu (in place fp32)
    bn_relu_kernel<false><<<OUTF / 32, dim3(32, 8)>>>(h2b, bn2_g, bn2_b, OUTF, nullptr, nullptr);

    // 14) mean pool + classifier
    head_kernel<<<BB, 512>>>(cls_w, cls_b, out);
}